// round 14
// baseline (speedup 1.0000x reference)
#include <cuda_runtime.h>
#include <cuda_fp16.h>
#include <cooperative_groups.h>
#include <cstdint>
namespace cg = cooperative_groups;

// ------------------------- scratch (device globals) -------------------------
#define BT (256*512)
__device__ float g_x64 [256*64];
__device__ float g_xg1f[(size_t)BT*512];
__device__ float g_xg1b[(size_t)BT*512];
__device__ float g_xg2f[(size_t)BT*256];
__device__ float g_xg2b[(size_t)BT*256];
__device__ float g_h2  [256*128];
__device__ __half g_xBhi[(size_t)BT*128];
__device__ __half g_xBlo[(size_t)BT*128];
__device__ __half g_Yhi [(size_t)BT*256];
__device__ __half g_Ylo [(size_t)BT*256];
__device__ __half g_wTh [4*65536];          // transposed weights [N,K], fp16

// ------------------------- small PTX helpers --------------------------------
__device__ __forceinline__ uint32_t smem_u32(const void* p) {
    uint32_t a;
    asm("{ .reg .u64 t; cvta.to.shared.u64 t, %1; cvt.u32.u64 %0, t; }" : "=r"(a) : "l"(p));
    return a;
}
__device__ __forceinline__ void mma_fp16(float* c, const uint32_t* a, const uint32_t* b) {
    asm volatile("mma.sync.aligned.m16n8k16.row.col.f32.f16.f16.f32 "
        "{%0,%1,%2,%3},{%4,%5,%6,%7},{%8,%9},{%0,%1,%2,%3};"
        : "+f"(c[0]), "+f"(c[1]), "+f"(c[2]), "+f"(c[3])
        : "r"(a[0]), "r"(a[1]), "r"(a[2]), "r"(a[3]), "r"(b[0]), "r"(b[1]));
}
#define LDMATRIX_X4(r0, r1, r2, r3, addr) \
    asm volatile("ldmatrix.sync.aligned.m8n8.x4.shared.b16 {%0,%1,%2,%3}, [%4];" \
        : "=r"(r0), "=r"(r1), "=r"(r2), "=r"(r3) : "r"(addr))
#define CP_ASYNC16(dst, src) asm volatile("cp.async.cg.shared.global [%0], [%1], 16;" :: "r"(dst), "l"(src))
#define CP_COMMIT()          asm volatile("cp.async.commit_group;" ::: "memory")
#define CP_WAIT(n)           asm volatile("cp.async.wait_group %0;" :: "n"(n) : "memory")

#define MBAR_INIT(mb, c) \
    asm volatile("mbarrier.init.shared.b64 [%0], %1;" :: "r"(mb), "r"(c) : "memory")
#define MBAR_ARRIVE_LOCAL(mb) \
    asm volatile("mbarrier.arrive.shared.b64 _, [%0];" :: "r"(mb) : "memory")
#define MBAR_ARRIVE_PEER(mb, peer) \
    asm volatile("{ .reg .b32 ra; mapa.shared::cluster.u32 ra, %0, %1;\n\t" \
                 "mbarrier.arrive.release.cluster.shared::cluster.b64 _, [ra]; }" \
                 :: "r"(mb), "r"(peer) : "memory")
#define MBAR_WAIT_CL(mb, ph) do { \
    uint32_t _m = (mb), _p = (ph), _d; \
    asm volatile("{ .reg .pred p; mbarrier.try_wait.parity.acquire.cluster.shared::cta.b64 p, [%1], %2, 0x989680; selp.b32 %0, 1, 0, p; }" \
        : "=r"(_d) : "r"(_m), "r"(_p) : "memory"); \
    if (!_d) { \
        asm volatile("{ .reg .pred P1;\n\tWL_%=: mbarrier.try_wait.parity.acquire.cluster.shared::cta.b64 P1, [%0], %1, 0x989680;\n\t@P1 bra.uni WD_%=;\n\tbra.uni WL_%=;\n\tWD_%=: }" \
            :: "r"(_m), "r"(_p) : "memory"); \
    } } while (0)

#define CLUSTER_ARRIVE() asm volatile("barrier.cluster.arrive.aligned;" ::: "memory")
#define CLUSTER_WAIT()   asm volatile("barrier.cluster.wait.aligned;" ::: "memory")

// fast sigmoid: 1/(1+2^(-x*log2e)) via ex2.approx + rcp.approx (~1e-6 rel err)
__device__ __forceinline__ float sigf(float x) {
    float r;
    asm("{ .reg .f32 t;\n\t"
        "mul.f32 t, %1, 0fBFB8AA3B;\n\t"
        "ex2.approx.f32 t, t;\n\t"
        "add.f32 t, t, 0f3F800000;\n\t"
        "rcp.approx.f32 %0, t; }"
        : "=f"(r) : "f"(x));
    return r;
}
__device__ __forceinline__ uint32_t pack_h2(__half a, __half b) {
    __half2 t = __halves2half2(a, b);
    return *(uint32_t*)&t;
}
__device__ __forceinline__ void split_h(float f, __half& hi, __half& lo) {
    hi = __float2half(f);
    lo = __float2half(f - __half2float(hi));
}

// --------- mega-prep: split inputB to fp16 hi/lo + transpose all weights ----
#define SPLIT_N4 (BT*128/4)
__global__ void __launch_bounds__(256)
prep_kernel(const float* __restrict__ inB, __half* __restrict__ hi, __half* __restrict__ lo,
            const float* __restrict__ k1f, const float* __restrict__ k1b,
            const float* __restrict__ k2f, const float* __restrict__ k2b,
            __half* __restrict__ wout)
{
    int idx = blockIdx.x * 256 + threadIdx.x;
    if (idx < SPLIT_N4) {
        float4 v = ((const float4*)inB)[idx];
        __half h0,h1,h2,h3,l0,l1,l2,l3;
        split_h(v.x,h0,l0); split_h(v.y,h1,l1);
        split_h(v.z,h2,l2); split_h(v.w,h3,l3);
        ((uint2*)hi)[idx] = make_uint2(pack_h2(h0,h1), pack_h2(h2,h3));
        ((uint2*)lo)[idx] = make_uint2(pack_h2(l0,l1), pack_h2(l2,l3));
    } else {
        int r = idx - SPLIT_N4;
        if (r < 4*65536) {
            int m = r >> 16, e = r & 65535;
            const float* src = (m == 0) ? k1f : (m == 1) ? k1b : (m == 2) ? k2f : k2b;
            int K = (m < 2) ? 128 : 256, N = (m < 2) ? 512 : 256;
            int n = e / K, k = e - n * K;
            wout[r] = __float2half(src[k * N + n]);
        }
    }
}

// ---- fp16 asymmetric 2-product GEMM + bias (unchanged) ---------------------
#define GSTAGE 30720
__global__ void __launch_bounds__(256, 2)
gemm_fp16_kernel(const __half* __restrict__ Ahi, const __half* __restrict__ Alo,
                 const __half* __restrict__ W,
                 const float* __restrict__ bias, float* __restrict__ C,
                 int M, int N, int K)
{
    extern __shared__ char smem[];
    const uint32_t smem_base = smem_u32(smem);
    const int tid = threadIdx.x;
    const int lane = tid & 31, wid = tid >> 5;
    const int m0 = blockIdx.x * 128, n0 = blockIdx.y * 128;
    const int wm = (wid >> 2) * 64, wn = (wid & 3) * 32;

    float acc[4][4][4];
    #pragma unroll
    for (int mt = 0; mt < 4; ++mt)
        #pragma unroll
        for (int nt = 0; nt < 4; ++nt)
            #pragma unroll
            for (int q = 0; q < 4; ++q) acc[mt][nt][q] = 0.f;

    const uint32_t lrow = (uint32_t)(lane & 15);
    const uint32_t lcol = (uint32_t)((lane >> 4) * 16);
    uint32_t offA[4], offB[2];
    #pragma unroll
    for (int mt = 0; mt < 4; ++mt)
        offA[mt] = (uint32_t)(wm + mt * 16 + lrow) * 80u + lcol;
    #pragma unroll
    for (int p = 0; p < 2; ++p)
        offB[p] = (uint32_t)(wn + p * 16 + lrow) * 80u + lcol;

    const int nch = K >> 5;
    auto issue = [&](int ch, int stage) {
        const int kc = ch << 5;
        const uint32_t st = smem_base + (uint32_t)stage * GSTAGE;
        #pragma unroll
        for (int i = 0; i < 2; ++i) {
            int idx = tid + i * 256;
            int row = idx >> 2, c = idx & 3;
            uint32_t soff = (uint32_t)(row * 80 + c * 16);
            size_t ga = (size_t)(m0 + row) * K + kc + c * 8;
            size_t gb = (size_t)(n0 + row) * K + kc + c * 8;
            CP_ASYNC16(st + soff,           Ahi + ga);
            CP_ASYNC16(st + 10240u + soff,  Alo + ga);
            CP_ASYNC16(st + 20480u + soff,  W   + gb);
        }
        CP_COMMIT();
    };

    issue(0, 0);
    for (int ch = 0; ch < nch; ++ch) {
        if (ch + 1 < nch) { issue(ch + 1, (ch + 1) & 1); CP_WAIT(1); }
        else             { CP_WAIT(0); }
        __syncthreads();

        const uint32_t stg = smem_base + (uint32_t)(ch & 1) * GSTAGE;
        #pragma unroll
        for (int kk = 0; kk < 2; ++kk) {
            const uint32_t kb = (uint32_t)(kk * 32);
            uint32_t bfr[4][2];
            #pragma unroll
            for (int p = 0; p < 2; ++p) {
                uint32_t r0, r1, r2, r3;
                LDMATRIX_X4(r0, r1, r2, r3, stg + 20480u + offB[p] + kb);
                bfr[2*p][0] = r0; bfr[2*p+1][0] = r1;
                bfr[2*p][1] = r2; bfr[2*p+1][1] = r3;
            }
            #pragma unroll
            for (int mt = 0; mt < 4; ++mt) {
                uint32_t ahi[4], alo[4];
                LDMATRIX_X4(ahi[0], ahi[1], ahi[2], ahi[3], stg + offA[mt] + kb);
                LDMATRIX_X4(alo[0], alo[1], alo[2], alo[3], stg + 10240u + offA[mt] + kb);
                #pragma unroll
                for (int nt = 0; nt < 4; ++nt) {
                    mma_fp16(acc[mt][nt], ahi, bfr[nt]);
                    mma_fp16(acc[mt][nt], alo, bfr[nt]);
                }
            }
        }
        __syncthreads();
    }

    #pragma unroll
    for (int mt = 0; mt < 4; ++mt) {
        int r = m0 + wm + mt * 16 + (lane >> 2);
        #pragma unroll
        for (int nt = 0; nt < 4; ++nt) {
            int col = n0 + wn + nt * 8 + (lane & 3) * 2;
            float b0 = __ldg(bias + col), b1 = __ldg(bias + col + 1);
            float2 v0 = make_float2(acc[mt][nt][0] + b0, acc[mt][nt][1] + b1);
            float2 v1 = make_float2(acc[mt][nt][2] + b0, acc[mt][nt][3] + b1);
            *(float2*)(C + (size_t)r * N + col)       = v0;
            *(float2*)(C + (size_t)(r + 8) * N + col) = v1;
        }
    }
}

// ------------------------- embedding MLP branch -----------------------------
__global__ void __launch_bounds__(256)
emb_mlp_kernel(const int* __restrict__ inputA, const float* __restrict__ emb,
               const float* __restrict__ w1, const float* __restrict__ b1,
               const float* __restrict__ w2, const float* __restrict__ b2,
               const float* __restrict__ w3, const float* __restrict__ b3,
               float* __restrict__ xout)
{
    __shared__ float x0[600], x1[256], x2[128];
    const int b = blockIdx.x, tid = threadIdx.x;
    for (int i = tid; i < 600; i += 256) {
        int la = i / 3, comp = i - la * 3;
        x0[i] = emb[inputA[b*200 + la]*3 + comp];
    }
    __syncthreads();
    {
        float acc = b1[tid];
        #pragma unroll 4
        for (int k = 0; k < 600; ++k) acc += x0[k] * w1[k*256 + tid];
        x1[tid] = fmaxf(acc, 0.f);
    }
    __syncthreads();
    if (tid < 128) {
        float acc = b2[tid];
        #pragma unroll 4
        for (int k = 0; k < 256; ++k) acc += x1[k] * w2[k*128 + tid];
        x2[tid] = fmaxf(acc, 0.f);
    }
    __syncthreads();
    if (tid < 64) {
        float acc = b3[tid];
        #pragma unroll 4
        for (int k = 0; k < 128; ++k) acc += x2[k] * w3[k*64 + tid];
        xout[b*64 + tid] = fmaxf(acc, 0.f);
    }
}

// ------------- LSTM layer 1 (H=128) — 4-CTA cluster, 512 threads ------------
// Each rank owns 32 h-indices (128 gate cols): per-warp per-step work halves
// vs R12. h broadcast to all 4 ranks' hbuf via DSMEM; count-4 mbar handshake.
#define XS1 516
#define HS1 136
__global__ void __cluster_dims__(4,1,1) __launch_bounds__(512, 1)
lstm1_mma_kernel(const float* __restrict__ xg1f, const float* __restrict__ xg1b,
                 const float* __restrict__ r1f,  const float* __restrict__ r1b,
                 __half* __restrict__ Yhi, __half* __restrict__ Ylo)
{
    extern __shared__ char smraw[];
    float*  sxg   = (float*)smraw;                               // 3*16*XS1 f32
    __half* hbufh = (__half*)(smraw + 3*16*XS1*4);               // 2*16*HS1 f16
    float*  ybuf  = (float*)(smraw + 3*16*XS1*4 + 2*16*HS1*2);   // 2*16*36 f32
    const uint32_t mbar = smem_u32(smraw + 3*16*XS1*4 + 2*16*HS1*2 + 2*16*36*4);

    cg::cluster_group cl = cg::this_cluster();
    const int rank = cl.block_rank();                  // 0..3
    const int dir  = blockIdx.y;
    const int b0   = (blockIdx.x >> 2) * 16;
    const int tid  = threadIdx.x;
    const int lane = tid & 31, w = tid >> 5;           // w in 0..15
    const int q    = lane & 3;
    const float* xg = dir ? xg1b : xg1f;
    const float* Wr = dir ? r1b : r1f;

    // fp16 weight fragments: warp covers 8 gate cols (single n8 tile)
    uint32_t bfr[8][2];
    {
        int n_local = w * 8 + (lane >> 2);
        int G = (n_local & 3) * 128 + rank * 32 + (n_local >> 2);
        #pragma unroll
        for (int kt = 0; kt < 8; ++kt)
            #pragma unroll
            for (int p = 0; p < 2; ++p) {
                int k = kt * 16 + q * 2 + p * 8;
                bfr[kt][p] = pack_h2(__float2half(Wr[k * 512 + G]),
                                     __float2half(Wr[(k + 1) * 512 + G]));
            }
    }

    for (int i = tid; i < 2 * 16 * HS1; i += 512) hbufh[i] = __float2half(0.f);
    if (tid == 0) MBAR_INIT(mbar, 4);

    const uint32_t hb32 = smem_u32(hbufh);
    const uint32_t xbase = smem_u32(sxg);
    const uint32_t lmbase = (uint32_t)(((lane & 15) * HS1 + ((lane >> 4) << 3)) * 2);
    const bool isState = (lane & 1);
    const int g0 = (q & 1) * 2;
    const int a_local = w * 2 + (q >> 1);
    const int colA = g0 * 128 + rank * 32 + a_local;
    const int hj   = rank * 32 + a_local;
    const int r = lane >> 2;

    float cst[2] = {0.f, 0.f};

    auto issue_xg = [&](int tt, int stage) {
        const uint32_t dst0 = xbase + (uint32_t)(stage * 16 * XS1 * 4);
        #pragma unroll
        for (int i = 0; i < 4; ++i) {
            int idx = tid + i * 512;
            int row = idx >> 7, c4 = idx & 127;
            CP_ASYNC16(dst0 + (uint32_t)((row * XS1 + c4 * 4) * 4),
                       xg + ((size_t)(b0 + row) * 512 + tt) * 512 + c4 * 4);
        }
        CP_COMMIT();
    };
    auto store_Y = [&](int tprev) {
        if (tid < 128) {
            const float* yb = ybuf + (tprev & 1) * 16 * 36;
            int row = tid >> 3, c4 = tid & 7;
            float4 v = *(const float4*)&yb[row * 36 + c4 * 4];
            int ttp = dir ? (511 - tprev) : tprev;
            size_t idx = ((size_t)(b0 + row) * 512 + ttp) * 256
                         + dir * 128 + rank * 32 + c4 * 4;
            __half h0,h1,h2,h3,l0,l1,l2,l3;
            split_h(v.x,h0,l0); split_h(v.y,h1,l1);
            split_h(v.z,h2,l2); split_h(v.w,h3,l3);
            *(uint2*)&Yhi[idx] = make_uint2(pack_h2(h0,h1), pack_h2(h2,h3));
            *(uint2*)&Ylo[idx] = make_uint2(pack_h2(l0,l1), pack_h2(l2,l3));
        }
    };

    // peer hbuf pointers (3 remote ranks)
    __half* peers[3];
    {
        int pi = 0;
        #pragma unroll
        for (int rr = 0; rr < 4; ++rr)
            if (rr != rank) peers[pi++] = (__half*)cl.map_shared_rank((void*)hbufh, rr);
    }
    __syncthreads();
    cl.sync();   // mbarrier init + hbuf zero visible cluster-wide

    issue_xg(dir ? 511 : 0, 0);
    issue_xg(dir ? 510 : 1, 1);
    CP_WAIT(1);  // stage 0 complete

    for (int t = 0; t < 512; ++t) {
        const int tt  = dir ? (511 - t) : t;
        const int cur = t & 1, nxt = cur ^ 1;

        __syncthreads();   // single barrier: publishes xg stage t, t-1 hbuf/ybuf

        if (t > 0) {
            if (tid == 0) {                     // release step t-1 stores
                MBAR_ARRIVE_LOCAL(mbar);
                #pragma unroll
                for (int rr = 0; rr < 4; ++rr)
                    if (rr != rank) MBAR_ARRIVE_PEER(mbar, rr);
            }
            store_Y(t - 1);
        }
        if (t + 2 < 512) issue_xg(dir ? (509 - t) : (t + 2), (t + 2) % 3);

        const float* xs = sxg + (t % 3) * 16 * XS1;
        float acc[4];
        acc[0] = xs[r * XS1 + colA];
        acc[1] = xs[r * XS1 + colA + 128];
        acc[2] = xs[(r + 8) * XS1 + colA];
        acc[3] = xs[(r + 8) * XS1 + colA + 128];

        if (t > 0) MBAR_WAIT_CL(mbar, (t - 1) & 1);   // all ranks' step t-1 h

        const uint32_t abase = hb32 + (uint32_t)(cur * 16 * HS1 * 2) + lmbase;
        #pragma unroll
        for (int kt = 0; kt < 8; ++kt) {
            uint32_t a0, a1, a2, a3;
            LDMATRIX_X4(a0, a1, a2, a3, abase + (uint32_t)(kt * 32));
            uint32_t afr[4] = {a0, a1, a2, a3};
            mma_fp16(acc, afr, bfr[kt]);
        }

        float* yb = ybuf + (t & 1) * 16 * 36;
        {
            float v0 = isState ? fmaxf(acc[0], 0.f) : sigf(acc[0]);
            float v1 = sigf(acc[1]);
            float v2 = isState ? fmaxf(acc[2], 0.f) : sigf(acc[2]);
            float v3 = sigf(acc[3]);
            float s0 = __shfl_xor_sync(0xffffffffu, v0, 1);
            float s1 = __shfl_xor_sync(0xffffffffu, v1, 1);
            float s2 = __shfl_xor_sync(0xffffffffu, v2, 1);
            float s3 = __shfl_xor_sync(0xffffffffu, v3, 1);
            if (isState) {
                float c0 = s1 * cst[0] + s0 * v0;
                float c1 = s3 * cst[1] + s2 * v2;
                cst[0] = c0; cst[1] = c1;
                float h0 = v1 * fmaxf(c0, 0.f);
                float h1 = v3 * fmaxf(c1, 0.f);
                __half h0h = __float2half(h0);
                __half h1h = __float2half(h1);
                int o0 = nxt * 16 * HS1 + r * HS1 + hj;
                int o1 = nxt * 16 * HS1 + (r + 8) * HS1 + hj;
                hbufh[o0] = h0h;      hbufh[o1] = h1h;
                peers[0][o0] = h0h;   peers[0][o1] = h1h;
                peers[1][o0] = h0h;   peers[1][o1] = h1h;
                peers[2][o0] = h0h;   peers[2][o1] = h1h;
                yb[r * 36 + a_local]       = h0;
                yb[(r + 8) * 36 + a_local] = h1;
            }
        }

        if (t + 2 < 512) { CP_WAIT(1); }
        else             { CP_WAIT(0); }
    }

    // keep CTA alive until peers' final-step DSMEM writes complete
    __syncthreads();
    CLUSTER_ARRIVE();
    store_Y(511);
    CLUSTER_WAIT();
}

// ------------- LSTM layer 2 (H=64) — 2-CTA cluster, 512 threads -------------
// Each rank owns 32 h (128 gate cols). Count-2 mbar handshake (R12-verified).
#define XS2 260
#define HS2 72
__global__ void __cluster_dims__(2,1,1) __launch_bounds__(512, 1)
lstm2_mma_kernel(const float* __restrict__ xg2f, const float* __restrict__ xg2b,
                 const float* __restrict__ r2f,  const float* __restrict__ r2b,
                 float* __restrict__ hout)
{
    extern __shared__ char smraw[];
    float*  sxg   = (float*)smraw;                     // 3*16*XS2 f32
    __half* hbufh = (__half*)(smraw + 3*16*XS2*4);     // 2*16*HS2 f16
    const uint32_t mbar = smem_u32(smraw + 3*16*XS2*4 + 2*16*HS2*2);

    cg::cluster_group cl = cg::this_cluster();
    const int rank = cl.block_rank();
    const int dir = blockIdx.y;
    const int b0  = (blockIdx.x >> 1) * 16;
    const int tid = threadIdx.x;
    const int lane = tid & 31, w = tid >> 5;           // 0..15
    const int q = lane & 3;
    const float* xg = dir ? xg2b : xg2f;
    const float* Wr = dir ? r2b : r2f;

    uint32_t bfr[4][2];
    {
        int n_local = w * 8 + (lane >> 2);
        int G = (n_local & 3) * 64 + rank * 32 + (n_local >> 2);
        #pragma unroll
        for (int kt = 0; kt < 4; ++kt)
            #pragma unroll
            for (int p = 0; p < 2; ++p) {
                int k = kt * 16 + q * 2 + p * 8;
                bfr[kt][p] = pack_h2(__float2half(Wr[k * 256 + G]),
                                     __float2half(Wr[(k + 1) * 256 + G]));
            }
    }

    for (int i = tid; i < 2 * 16 * HS2; i += 512) hbufh[i] = __float2half(0.f);
    if (tid == 0) MBAR_INIT(mbar, 2);

    const uint32_t hb32 = smem_u32(hbufh);
    const uint32_t xbase = smem_u32(sxg);
    const uint32_t lmbase = (uint32_t)(((lane & 15) * HS2 + ((lane >> 4) << 3)) * 2);
    const bool isState = (lane & 1);
    const int g0 = (q & 1) * 2;
    const int a_local = w * 2 + (q >> 1);
    const int colA = g0 * 64 + rank * 32 + a_local;
    const int hj   = rank * 32 + a_local;
    const int r = lane >> 2;

    float cst[2] = {0.f, 0.f};

    auto issue_xg = [&](int tt, int stage) {
        const uint32_t dst0 = xbase + (uint32_t)(stage * 16 * XS2 * 4);
        #pragma unroll
        for (int i = 0; i < 2; ++i) {
            int idx = tid + i * 512;
            int row = idx >> 6, c4 = idx & 63;
            CP_ASYNC16(dst0 + (uint32_t)((row * XS2 + c4 * 4) * 4),
                       xg + ((size_t)(b0 + row) * 512 + tt) * 256 + c4 * 4);
        }
        CP_COMMIT();
    };

    __half* peer_h = (__half*)cl.map_shared_rank((void*)hbufh, rank ^ 1);
    __syncthreads();
    cl.sync();

    issue_xg(dir ? 511 : 0, 0);
    issue_xg(dir ? 510 : 1, 1);
    CP_WAIT(1);

    for (int t = 0; t < 512; ++t) {
        const int tt  = dir ? (511 - t) : t;
        const int cur = t & 1, nxt = cur ^ 1;

        __syncthreads();

        if (t > 0 && tid == 0) {
            MBAR_ARRIVE_LOCAL(mbar);
            MBAR_ARRIVE_PEER(mbar, rank ^ 1);
        }
        if (t + 2 < 512) issue_xg(dir ? (509 - t) : (t + 2), (t + 2) % 3);

        const float* xs = sxg + (t % 3) * 16 * XS2;
        float acc[4];
        acc[0] = xs[r * XS2 + colA];
        acc[1] = xs[r * XS2 + colA + 64];
        acc[2] = xs[(r + 8) * XS2 + colA];
        acc[3] = xs[(r + 8) * XS2 + colA + 64];

        if (t > 0) MBAR_WAIT_CL(mbar, (t - 1) & 1);

        const uint32_t abase = hb32 + (uint32_t)(cur * 16 * HS2 * 2) + lmbase;
        #pragma unroll
        for (int kt = 0; kt < 4; ++kt) {
            uint32_t a0, a1, a2, a3;
            LDMATRIX_X4(a0, a1, a2, a3, abase + (uint32_t)(kt * 32));
            uint32_t afr[4] = {a0, a1, a2, a3};
            mma_fp16(acc, afr, bfr[kt]);
        }

        {
            float v0 = isState ? fmaxf(acc[0], 0.f) : sigf(acc[0]);
            float v1 = sigf(acc[1]);
            float v2 = isState ? fmaxf(acc[2], 0.f) : sigf(acc[2]);
            float v3 = sigf(acc[3]);
            float s0 = __shfl_xor_sync(0xffffffffu, v0, 1);
            float s1 = __shfl_xor_sync(0xffffffffu, v1, 1);
            float s2 = __shfl_xor_sync(0xffffffffu, v2, 1);
            float s3 = __shfl_xor_sync(0xffffffffu, v3, 1);
            if (isState) {
                float c0 = s1 * cst[0] + s0 * v0;
                float c1 = s3 * cst[1] + s2 * v2;
                cst[0] = c0; cst[1] = c1;
                float h0 = v1 * fmaxf(c0, 0.f);
                float h1 = v3 * fmaxf(c1, 0.f);
                __half h0h = __float2half(h0);
                __half h1h = __float2half(h1);
                int o0 = nxt * 16 * HS2 + r * HS2 + hj;
                int o1 = nxt * 16 * HS2 + (r + 8) * HS2 + hj;
                hbufh[o0] = h0h;   hbufh[o1] = h1h;
                peer_h[o0] = h0h;  peer_h[o1] = h1h;
                if (t == 511) {
                    hout[(size_t)(b0 + r) * 128 + dir * 64 + hj]     = h0;
                    hout[(size_t)(b0 + r + 8) * 128 + dir * 64 + hj] = h1;
                }
            }
        }

        if (t + 2 < 512) { CP_WAIT(1); }
        else             { CP_WAIT(0); }
    }

    // keep CTA alive until peer's final-step DSMEM writes complete
    CLUSTER_ARRIVE();
    CLUSTER_WAIT();
}

// ------------------------------ heads ---------------------------------------
__global__ void __launch_bounds__(256)
head_kernel(const float* __restrict__ x64, const float* __restrict__ h2,
            const float* __restrict__ wz1, const float* __restrict__ bz1,
            const float* __restrict__ wz2, const float* __restrict__ bz2,
            const float* __restrict__ wt1, const float* __restrict__ bt1,
            const float* __restrict__ wt2, const float* __restrict__ bt2,
            float* __restrict__ out)
{
    const int b = threadIdx.x;
    float comb[192];
    #pragma unroll 4
    for (int k = 0; k < 64; ++k)  comb[k]      = x64[b*64 + k];
    #pragma unroll 4
    for (int k = 0; k < 128; ++k) comb[64 + k] = h2[b*128 + k];

    float z0 = bz1[0], z1 = bz1[1], t0 = bt1[0], t1 = bt1[1];
    #pragma unroll 4
    for (int k = 0; k < 192; ++k) {
        float v = comb[k];
        z0 += v * wz1[k*2 + 0]; z1 += v * wz1[k*2 + 1];
        t0 += v * wt1[k*2 + 0]; t1 += v * wt1[k*2 + 1];
    }
    out[b]       = fmaxf(z0,0.f)*wz2[0] + fmaxf(z1,0.f)*wz2[1] + bz2[0];
    out[256 + b] = fmaxf(t0,0.f)*wt2[0] + fmaxf(t1,0.f)*wt2[1] + bt2[0];
}

// ------------------------------ launcher ------------------------------------
extern "C" void kernel_launch(void* const* d_in, const int* in_sizes, int n_in,
                              void* d_out, int out_size)
{
    const int*   inputA = (const int*)  d_in[0];
    const float* inputB = (const float*)d_in[1];
    const float* emb = (const float*)d_in[2];
    const float *w1=(const float*)d_in[3],  *b1=(const float*)d_in[4];
    const float *w2=(const float*)d_in[5],  *b2=(const float*)d_in[6];
    const float *w3=(const float*)d_in[7],  *b3=(const float*)d_in[8];
    const float *k1f=(const float*)d_in[9],  *r1f=(const float*)d_in[10], *bb1f=(const float*)d_in[11];
    const float *k1b=(const float*)d_in[12], *r1b=(const float*)d_in[13], *bb1b=(const float*)d_in[14];
    const float *k2f=(const float*)d_in[15], *r2f=(const float*)d_in[16], *bb2f=(const float*)d_in[17];
    const float *k2b=(const float*)d_in[18], *r2b=(const float*)d_in[19], *bb2b=(const float*)d_in[20];
    const float *wz1=(const float*)d_in[21], *bz1=(const float*)d_in[22];
    const float *wz2=(const float*)d_in[23], *bz2=(const float*)d_in[24];
    const float *wt1=(const float*)d_in[25], *bt1=(const float*)d_in[26];
    const float *wt2=(const float*)d_in[27], *bt2=(const float*)d_in[28];
    float* out = (float*)d_out;

    float *xg1f, *xg1b, *xg2f, *xg2b, *x64, *h2;
    __half *xBhi, *xBlo, *Yhi, *Ylo, *wTh;
    cudaGetSymbolAddress((void**)&xg1f, g_xg1f);
    cudaGetSymbolAddress((void**)&xg1b, g_xg1b);
    cudaGetSymbolAddress((void**)&xg2f, g_xg2f);
    cudaGetSymbolAddress((void**)&xg2b, g_xg2b);
    cudaGetSymbolAddress((void**)&x64,  g_x64);
    cudaGetSymbolAddress((void**)&h2,   g_h2);
    cudaGetSymbolAddress((void**)&xBhi, g_xBhi);
    cudaGetSymbolAddress((void**)&xBlo, g_xBlo);
    cudaGetSymbolAddress((void**)&Yhi,  g_Yhi);
    cudaGetSymbolAddress((void**)&Ylo,  g_Ylo);
    cudaGetSymbolAddress((void**)&wTh,  g_wTh);

    __half *w1fh = wTh,            *w1bh = wTh + 65536;
    __half *w2fh = wTh + 2*65536,  *w2bh = wTh + 3*65536;

    const size_t sm1 = (size_t)(3*16*XS1*4 + 2*16*HS1*2 + 2*16*36*4 + 16);
    const size_t sm2 = (size_t)(3*16*XS2*4 + 2*16*HS2*2 + 16);

    static bool attr_done = false;
    if (!attr_done) {
        cudaFuncSetAttribute(gemm_fp16_kernel, cudaFuncAttributeMaxDynamicSharedMemorySize, 2*GSTAGE);
        cudaFuncSetAttribute(lstm1_mma_kernel, cudaFuncAttributeMaxDynamicSharedMemorySize, (int)sm1);
        cudaFuncSetAttribute(lstm2_mma_kernel, cudaFuncAttributeMaxDynamicSharedMemorySize, (int)sm2);
        attr_done = true;
    }

    prep_kernel<<<(SPLIT_N4 + 4*65536 + 255)/256, 256>>>(inputB, xBhi, xBlo,
                                                         k1f, k1b, k2f, k2b, wTh);  // 0
    const size_t gsm = 2*GSTAGE;
    gemm_fp16_kernel<<<dim3(1024,4), 256, gsm>>>(xBhi, xBlo, w1fh, bb1f, xg1f, BT, 512, 128); // 1
    gemm_fp16_kernel<<<dim3(1024,4), 256, gsm>>>(xBhi, xBlo, w1bh, bb1b, xg1b, BT, 512, 128); // 2

    lstm1_mma_kernel<<<dim3(64,2), 512, sm1>>>(xg1f, xg1b, r1f, r1b, Yhi, Ylo);     // 3

    gemm_fp16_kernel<<<dim3(1024,2), 256, gsm>>>(Yhi, Ylo, w2fh, bb2f, xg2f, BT, 256, 256);   // 4
    gemm_fp16_kernel<<<dim3(1024,2), 256, gsm>>>(Yhi, Ylo, w2bh, bb2b, xg2b, BT, 256, 256);   // 5

    lstm2_mma_kernel<<<dim3(32,2), 512, sm2>>>(xg2f, xg2b, r2f, r2b, h2);           // 6

    emb_mlp_kernel<<<256, 256>>>(inputA, emb, w1,b1, w2,b2, w3,b3, x64);            // 7
    head_kernel<<<1, 256>>>(x64, h2, wz1,bz1, wz2,bz2, wt1,bt1, wt2,bt2, out);      // 8
}

// round 15
// speedup vs baseline: 1.1618x; 1.1618x over previous
#include <cuda_runtime.h>
#include <cuda_fp16.h>
#include <cooperative_groups.h>
#include <cstdint>
namespace cg = cooperative_groups;

// ------------------------- scratch (device globals) -------------------------
#define BT (256*512)
__device__ float g_x64 [256*64];
__device__ float g_xg1f[(size_t)BT*512];
__device__ float g_xg1b[(size_t)BT*512];
__device__ float g_xg2f[(size_t)BT*256];
__device__ float g_xg2b[(size_t)BT*256];
__device__ float g_h2  [256*128];
__device__ __half g_xBhi[(size_t)BT*128];
__device__ __half g_xBlo[(size_t)BT*128];
__device__ __half g_Yhi [(size_t)BT*256];
__device__ __half g_Ylo [(size_t)BT*256];
__device__ __half g_wTh [4*65536];          // transposed weights [N,K], fp16

// ------------------------- small PTX helpers --------------------------------
__device__ __forceinline__ uint32_t smem_u32(const void* p) {
    uint32_t a;
    asm("{ .reg .u64 t; cvta.to.shared.u64 t, %1; cvt.u32.u64 %0, t; }" : "=r"(a) : "l"(p));
    return a;
}
__device__ __forceinline__ void mma_fp16(float* c, const uint32_t* a, const uint32_t* b) {
    asm volatile("mma.sync.aligned.m16n8k16.row.col.f32.f16.f16.f32 "
        "{%0,%1,%2,%3},{%4,%5,%6,%7},{%8,%9},{%0,%1,%2,%3};"
        : "+f"(c[0]), "+f"(c[1]), "+f"(c[2]), "+f"(c[3])
        : "r"(a[0]), "r"(a[1]), "r"(a[2]), "r"(a[3]), "r"(b[0]), "r"(b[1]));
}
#define LDMATRIX_X4(r0, r1, r2, r3, addr) \
    asm volatile("ldmatrix.sync.aligned.m8n8.x4.shared.b16 {%0,%1,%2,%3}, [%4];" \
        : "=r"(r0), "=r"(r1), "=r"(r2), "=r"(r3) : "r"(addr))
#define CP_ASYNC16(dst, src) asm volatile("cp.async.cg.shared.global [%0], [%1], 16;" :: "r"(dst), "l"(src))
#define CP_COMMIT()          asm volatile("cp.async.commit_group;" ::: "memory")
#define CP_WAIT(n)           asm volatile("cp.async.wait_group %0;" :: "n"(n) : "memory")

#define MBAR_INIT(mb, c) \
    asm volatile("mbarrier.init.shared.b64 [%0], %1;" :: "r"(mb), "r"(c) : "memory")
#define MBAR_ARRIVE_LOCAL(mb) \
    asm volatile("mbarrier.arrive.shared.b64 _, [%0];" :: "r"(mb) : "memory")
#define MBAR_ARRIVE_PEER(mb, peer) \
    asm volatile("{ .reg .b32 ra; mapa.shared::cluster.u32 ra, %0, %1;\n\t" \
                 "mbarrier.arrive.release.cluster.shared::cluster.b64 _, [ra]; }" \
                 :: "r"(mb), "r"(peer) : "memory")
#define MBAR_WAIT_CL(mb, ph) do { \
    uint32_t _m = (mb), _p = (ph), _d; \
    asm volatile("{ .reg .pred p; mbarrier.try_wait.parity.acquire.cluster.shared::cta.b64 p, [%1], %2, 0x989680; selp.b32 %0, 1, 0, p; }" \
        : "=r"(_d) : "r"(_m), "r"(_p) : "memory"); \
    if (!_d) { \
        asm volatile("{ .reg .pred P1;\n\tWL_%=: mbarrier.try_wait.parity.acquire.cluster.shared::cta.b64 P1, [%0], %1, 0x989680;\n\t@P1 bra.uni WD_%=;\n\tbra.uni WL_%=;\n\tWD_%=: }" \
            :: "r"(_m), "r"(_p) : "memory"); \
    } } while (0)

#define CLUSTER_ARRIVE() asm volatile("barrier.cluster.arrive.aligned;" ::: "memory")
#define CLUSTER_WAIT()   asm volatile("barrier.cluster.wait.aligned;" ::: "memory")

// fast sigmoid: 1/(1+2^(-x*log2e)) via ex2.approx + rcp.approx (~1e-6 rel err)
__device__ __forceinline__ float sigf(float x) {
    float r;
    asm("{ .reg .f32 t;\n\t"
        "mul.f32 t, %1, 0fBFB8AA3B;\n\t"
        "ex2.approx.f32 t, t;\n\t"
        "add.f32 t, t, 0f3F800000;\n\t"
        "rcp.approx.f32 %0, t; }"
        : "=f"(r) : "f"(x));
    return r;
}
__device__ __forceinline__ uint32_t pack_h2(__half a, __half b) {
    __half2 t = __halves2half2(a, b);
    return *(uint32_t*)&t;
}
__device__ __forceinline__ void split_h(float f, __half& hi, __half& lo) {
    hi = __float2half(f);
    lo = __float2half(f - __half2float(hi));
}

// --------- mega-prep: split inputB to fp16 hi/lo + transpose all weights ----
#define SPLIT_N4 (BT*128/4)
__global__ void __launch_bounds__(256)
prep_kernel(const float* __restrict__ inB, __half* __restrict__ hi, __half* __restrict__ lo,
            const float* __restrict__ k1f, const float* __restrict__ k1b,
            const float* __restrict__ k2f, const float* __restrict__ k2b,
            __half* __restrict__ wout)
{
    int idx = blockIdx.x * 256 + threadIdx.x;
    if (idx < SPLIT_N4) {
        float4 v = ((const float4*)inB)[idx];
        __half h0,h1,h2,h3,l0,l1,l2,l3;
        split_h(v.x,h0,l0); split_h(v.y,h1,l1);
        split_h(v.z,h2,l2); split_h(v.w,h3,l3);
        ((uint2*)hi)[idx] = make_uint2(pack_h2(h0,h1), pack_h2(h2,h3));
        ((uint2*)lo)[idx] = make_uint2(pack_h2(l0,l1), pack_h2(l2,l3));
    } else {
        int r = idx - SPLIT_N4;
        if (r < 4*65536) {
            int m = r >> 16, e = r & 65535;
            const float* src = (m == 0) ? k1f : (m == 1) ? k1b : (m == 2) ? k2f : k2b;
            int K = (m < 2) ? 128 : 256, N = (m < 2) ? 512 : 256;
            int n = e / K, k = e - n * K;
            wout[r] = __float2half(src[k * N + n]);
        }
    }
}

// ---- fp16 asymmetric 2-product GEMM + bias (unchanged) ---------------------
#define GSTAGE 30720
__global__ void __launch_bounds__(256, 2)
gemm_fp16_kernel(const __half* __restrict__ Ahi, const __half* __restrict__ Alo,
                 const __half* __restrict__ W,
                 const float* __restrict__ bias, float* __restrict__ C,
                 int M, int N, int K)
{
    extern __shared__ char smem[];
    const uint32_t smem_base = smem_u32(smem);
    const int tid = threadIdx.x;
    const int lane = tid & 31, wid = tid >> 5;
    const int m0 = blockIdx.x * 128, n0 = blockIdx.y * 128;
    const int wm = (wid >> 2) * 64, wn = (wid & 3) * 32;

    float acc[4][4][4];
    #pragma unroll
    for (int mt = 0; mt < 4; ++mt)
        #pragma unroll
        for (int nt = 0; nt < 4; ++nt)
            #pragma unroll
            for (int q = 0; q < 4; ++q) acc[mt][nt][q] = 0.f;

    const uint32_t lrow = (uint32_t)(lane & 15);
    const uint32_t lcol = (uint32_t)((lane >> 4) * 16);
    uint32_t offA[4], offB[2];
    #pragma unroll
    for (int mt = 0; mt < 4; ++mt)
        offA[mt] = (uint32_t)(wm + mt * 16 + lrow) * 80u + lcol;
    #pragma unroll
    for (int p = 0; p < 2; ++p)
        offB[p] = (uint32_t)(wn + p * 16 + lrow) * 80u + lcol;

    const int nch = K >> 5;
    auto issue = [&](int ch, int stage) {
        const int kc = ch << 5;
        const uint32_t st = smem_base + (uint32_t)stage * GSTAGE;
        #pragma unroll
        for (int i = 0; i < 2; ++i) {
            int idx = tid + i * 256;
            int row = idx >> 2, c = idx & 3;
            uint32_t soff = (uint32_t)(row * 80 + c * 16);
            size_t ga = (size_t)(m0 + row) * K + kc + c * 8;
            size_t gb = (size_t)(n0 + row) * K + kc + c * 8;
            CP_ASYNC16(st + soff,           Ahi + ga);
            CP_ASYNC16(st + 10240u + soff,  Alo + ga);
            CP_ASYNC16(st + 20480u + soff,  W   + gb);
        }
        CP_COMMIT();
    };

    issue(0, 0);
    for (int ch = 0; ch < nch; ++ch) {
        if (ch + 1 < nch) { issue(ch + 1, (ch + 1) & 1); CP_WAIT(1); }
        else             { CP_WAIT(0); }
        __syncthreads();

        const uint32_t stg = smem_base + (uint32_t)(ch & 1) * GSTAGE;
        #pragma unroll
        for (int kk = 0; kk < 2; ++kk) {
            const uint32_t kb = (uint32_t)(kk * 32);
            uint32_t bfr[4][2];
            #pragma unroll
            for (int p = 0; p < 2; ++p) {
                uint32_t r0, r1, r2, r3;
                LDMATRIX_X4(r0, r1, r2, r3, stg + 20480u + offB[p] + kb);
                bfr[2*p][0] = r0; bfr[2*p+1][0] = r1;
                bfr[2*p][1] = r2; bfr[2*p+1][1] = r3;
            }
            #pragma unroll
            for (int mt = 0; mt < 4; ++mt) {
                uint32_t ahi[4], alo[4];
                LDMATRIX_X4(ahi[0], ahi[1], ahi[2], ahi[3], stg + offA[mt] + kb);
                LDMATRIX_X4(alo[0], alo[1], alo[2], alo[3], stg + 10240u + offA[mt] + kb);
                #pragma unroll
                for (int nt = 0; nt < 4; ++nt) {
                    mma_fp16(acc[mt][nt], ahi, bfr[nt]);
                    mma_fp16(acc[mt][nt], alo, bfr[nt]);
                }
            }
        }
        __syncthreads();
    }

    #pragma unroll
    for (int mt = 0; mt < 4; ++mt) {
        int r = m0 + wm + mt * 16 + (lane >> 2);
        #pragma unroll
        for (int nt = 0; nt < 4; ++nt) {
            int col = n0 + wn + nt * 8 + (lane & 3) * 2;
            float b0 = __ldg(bias + col), b1 = __ldg(bias + col + 1);
            float2 v0 = make_float2(acc[mt][nt][0] + b0, acc[mt][nt][1] + b1);
            float2 v1 = make_float2(acc[mt][nt][2] + b0, acc[mt][nt][3] + b1);
            *(float2*)(C + (size_t)r * N + col)       = v0;
            *(float2*)(C + (size_t)(r + 8) * N + col) = v1;
        }
    }
}

// ------------------------- embedding MLP branch -----------------------------
__global__ void __launch_bounds__(256)
emb_mlp_kernel(const int* __restrict__ inputA, const float* __restrict__ emb,
               const float* __restrict__ w1, const float* __restrict__ b1,
               const float* __restrict__ w2, const float* __restrict__ b2,
               const float* __restrict__ w3, const float* __restrict__ b3,
               float* __restrict__ xout)
{
    __shared__ float x0[600], x1[256], x2[128];
    const int b = blockIdx.x, tid = threadIdx.x;
    for (int i = tid; i < 600; i += 256) {
        int la = i / 3, comp = i - la * 3;
        x0[i] = emb[inputA[b*200 + la]*3 + comp];
    }
    __syncthreads();
    {
        float acc = b1[tid];
        #pragma unroll 4
        for (int k = 0; k < 600; ++k) acc += x0[k] * w1[k*256 + tid];
        x1[tid] = fmaxf(acc, 0.f);
    }
    __syncthreads();
    if (tid < 128) {
        float acc = b2[tid];
        #pragma unroll 4
        for (int k = 0; k < 256; ++k) acc += x1[k] * w2[k*128 + tid];
        x2[tid] = fmaxf(acc, 0.f);
    }
    __syncthreads();
    if (tid < 64) {
        float acc = b3[tid];
        #pragma unroll 4
        for (int k = 0; k < 128; ++k) acc += x2[k] * w3[k*64 + tid];
        xout[b*64 + tid] = fmaxf(acc, 0.f);
    }
}

// ------ LSTM layer 1 (H=128) — 2-CTA cluster (R12 topology), 1024 threads ---
// 32 warps (8/SMSP, occ 50%); each warp covers 8 gate cols (nt=1).
// Comm pattern identical to R12 (count-2 mbar handshake, single peer).
#define XS1 516
#define HS1 136
__global__ void __cluster_dims__(2,1,1) __launch_bounds__(1024, 1)
lstm1_mma_kernel(const float* __restrict__ xg1f, const float* __restrict__ xg1b,
                 const float* __restrict__ r1f,  const float* __restrict__ r1b,
                 __half* __restrict__ Yhi, __half* __restrict__ Ylo)
{
    extern __shared__ char smraw[];
    float*  sxg   = (float*)smraw;                               // 3*16*XS1 f32
    __half* hbufh = (__half*)(smraw + 3*16*XS1*4);               // 2*16*HS1 f16
    float*  ybuf  = (float*)(smraw + 3*16*XS1*4 + 2*16*HS1*2);   // 2*16*68 f32
    const uint32_t mbar = smem_u32(smraw + 3*16*XS1*4 + 2*16*HS1*2 + 2*16*68*4);

    cg::cluster_group cl = cg::this_cluster();
    const int rank = cl.block_rank();
    const int dir  = blockIdx.y;
    const int b0   = (blockIdx.x >> 1) * 16;
    const int tid  = threadIdx.x;
    const int lane = tid & 31, w = tid >> 5;          // w in 0..31
    const int q    = lane & 3;
    const float* xg = dir ? xg1b : xg1f;
    const float* Wr = dir ? r1b : r1f;

    // fp16 weight fragments: warp covers 8 gate cols (single n8 tile)
    uint32_t bfr[8][2];
    {
        int n_local = w * 8 + (lane >> 2);            // 0..255
        int G = (n_local & 3) * 128 + rank * 64 + (n_local >> 2);
        #pragma unroll
        for (int kt = 0; kt < 8; ++kt)
            #pragma unroll
            for (int p = 0; p < 2; ++p) {
                int k = kt * 16 + q * 2 + p * 8;
                bfr[kt][p] = pack_h2(__float2half(Wr[k * 512 + G]),
                                     __float2half(Wr[(k + 1) * 512 + G]));
            }
    }

    for (int i = tid; i < 2 * 16 * HS1; i += 1024) hbufh[i] = __float2half(0.f);
    if (tid == 0) MBAR_INIT(mbar, 2);

    const uint32_t hb32 = smem_u32(hbufh);
    const uint32_t xbase = smem_u32(sxg);
    const uint32_t lmbase = (uint32_t)(((lane & 15) * HS1 + ((lane >> 4) << 3)) * 2);
    const bool isState = (lane & 1);
    const int g0 = (q & 1) * 2;
    const int a_local = w * 2 + (q >> 1);             // 0..63
    const int colA = g0 * 128 + rank * 64 + a_local;
    const int hj   = rank * 64 + a_local;
    const int r = lane >> 2;

    float cst[2] = {0.f, 0.f};

    auto issue_xg = [&](int tt, int stage) {
        const uint32_t dst0 = xbase + (uint32_t)(stage * 16 * XS1 * 4);
        #pragma unroll
        for (int i = 0; i < 2; ++i) {                 // 2048 float4 / 1024 thr
            int idx = tid + i * 1024;
            int row = idx >> 7, c4 = idx & 127;
            CP_ASYNC16(dst0 + (uint32_t)((row * XS1 + c4 * 4) * 4),
                       xg + ((size_t)(b0 + row) * 512 + tt) * 512 + c4 * 4);
        }
        CP_COMMIT();
    };
    auto store_Y = [&](int tprev) {
        if (tid < 256) {
            const float* yb = ybuf + (tprev & 1) * 16 * 68;
            int row = tid >> 4, c4 = tid & 15;
            float4 v = *(const float4*)&yb[row * 68 + c4 * 4];
            int ttp = dir ? (511 - tprev) : tprev;
            size_t idx = ((size_t)(b0 + row) * 512 + ttp) * 256
                         + dir * 128 + rank * 64 + c4 * 4;
            __half h0,h1,h2,h3,l0,l1,l2,l3;
            split_h(v.x,h0,l0); split_h(v.y,h1,l1);
            split_h(v.z,h2,l2); split_h(v.w,h3,l3);
            *(uint2*)&Yhi[idx] = make_uint2(pack_h2(h0,h1), pack_h2(h2,h3));
            *(uint2*)&Ylo[idx] = make_uint2(pack_h2(l0,l1), pack_h2(l2,l3));
        }
    };

    __half* peer_h = (__half*)cl.map_shared_rank((void*)hbufh, rank ^ 1);
    __syncthreads();
    cl.sync();   // mbarrier init + hbuf zero visible cluster-wide

    issue_xg(dir ? 511 : 0, 0);
    issue_xg(dir ? 510 : 1, 1);
    CP_WAIT(1);  // stage 0 complete

    for (int t = 0; t < 512; ++t) {
        const int tt  = dir ? (511 - t) : t;
        const int cur = t & 1, nxt = cur ^ 1;

        __syncthreads();   // single barrier: publishes xg stage t, t-1 hbuf/ybuf

        if (t > 0) {
            if (tid == 0) {                     // release step t-1 stores to peer
                MBAR_ARRIVE_LOCAL(mbar);
                MBAR_ARRIVE_PEER(mbar, rank ^ 1);
            }
            store_Y(t - 1);
        }
        if (t + 2 < 512) issue_xg(dir ? (509 - t) : (t + 2), (t + 2) % 3);

        const float* xs = sxg + (t % 3) * 16 * XS1;
        float acc[4];
        acc[0] = xs[r * XS1 + colA];
        acc[1] = xs[r * XS1 + colA + 128];
        acc[2] = xs[(r + 8) * XS1 + colA];
        acc[3] = xs[(r + 8) * XS1 + colA + 128];

        if (t > 0) MBAR_WAIT_CL(mbar, (t - 1) & 1);

        const uint32_t abase = hb32 + (uint32_t)(cur * 16 * HS1 * 2) + lmbase;
        #pragma unroll
        for (int kt = 0; kt < 8; ++kt) {
            uint32_t a0, a1, a2, a3;
            LDMATRIX_X4(a0, a1, a2, a3, abase + (uint32_t)(kt * 32));
            uint32_t afr[4] = {a0, a1, a2, a3};
            mma_fp16(acc, afr, bfr[kt]);
        }

        float* yb = ybuf + (t & 1) * 16 * 68;
        {
            float v0 = isState ? fmaxf(acc[0], 0.f) : sigf(acc[0]);
            float v1 = sigf(acc[1]);
            float v2 = isState ? fmaxf(acc[2], 0.f) : sigf(acc[2]);
            float v3 = sigf(acc[3]);
            float s0 = __shfl_xor_sync(0xffffffffu, v0, 1);
            float s1 = __shfl_xor_sync(0xffffffffu, v1, 1);
            float s2 = __shfl_xor_sync(0xffffffffu, v2, 1);
            float s3 = __shfl_xor_sync(0xffffffffu, v3, 1);
            if (isState) {
                float c0 = s1 * cst[0] + s0 * v0;
                float c1 = s3 * cst[1] + s2 * v2;
                cst[0] = c0; cst[1] = c1;
                float h0 = v1 * fmaxf(c0, 0.f);
                float h1 = v3 * fmaxf(c1, 0.f);
                __half h0h = __float2half(h0);
                __half h1h = __float2half(h1);
                int o0 = nxt * 16 * HS1 + r * HS1 + hj;
                int o1 = nxt * 16 * HS1 + (r + 8) * HS1 + hj;
                hbufh[o0] = h0h;  hbufh[o1] = h1h;
                peer_h[o0] = h0h; peer_h[o1] = h1h;
                yb[r * 68 + a_local]       = h0;
                yb[(r + 8) * 68 + a_local] = h1;
            }
        }

        if (t + 2 < 512) { CP_WAIT(1); }
        else             { CP_WAIT(0); }
    }

    // keep CTA alive until peer's final-step DSMEM writes complete
    __syncthreads();
    CLUSTER_ARRIVE();
    store_Y(511);
    CLUSTER_WAIT();
}

// ------ LSTM layer 2 (H=64) — single CTA (R12 topology), 1024 threads -------
#define XS2 260
#define HS2 72
__global__ void __launch_bounds__(1024, 1)
lstm2_mma_kernel(const float* __restrict__ xg2f, const float* __restrict__ xg2b,
                 const float* __restrict__ r2f,  const float* __restrict__ r2b,
                 float* __restrict__ hout)
{
    extern __shared__ char smraw[];
    float*  sxg   = (float*)smraw;                     // 3*16*XS2 f32
    __half* hbufh = (__half*)(smraw + 3*16*XS2*4);     // 2*16*HS2 f16

    const int dir = blockIdx.y;
    const int b0  = blockIdx.x * 16;
    const int tid = threadIdx.x;
    const int lane = tid & 31, w = tid >> 5;           // 0..31
    const int q = lane & 3;
    const float* xg = dir ? xg2b : xg2f;
    const float* Wr = dir ? r2b : r2f;

    uint32_t bfr[4][2];
    {
        int n_local = w * 8 + (lane >> 2);             // 0..255
        int G = (n_local & 3) * 64 + (n_local >> 2);
        #pragma unroll
        for (int kt = 0; kt < 4; ++kt)
            #pragma unroll
            for (int p = 0; p < 2; ++p) {
                int k = kt * 16 + q * 2 + p * 8;
                bfr[kt][p] = pack_h2(__float2half(Wr[k * 256 + G]),
                                     __float2half(Wr[(k + 1) * 256 + G]));
            }
    }

    for (int i = tid; i < 2 * 16 * HS2; i += 1024) hbufh[i] = __float2half(0.f);

    const uint32_t hb32 = smem_u32(hbufh);
    const uint32_t xbase = smem_u32(sxg);
    const uint32_t lmbase = (uint32_t)(((lane & 15) * HS2 + ((lane >> 4) << 3)) * 2);
    const bool isState = (lane & 1);
    const int g0 = (q & 1) * 2;
    const int a_local = w * 2 + (q >> 1);              // 0..63
    const int colA = g0 * 64 + a_local;
    const int hj   = a_local;
    const int r = lane >> 2;

    float cst[2] = {0.f, 0.f};

    auto issue_xg = [&](int tt, int stage) {
        const uint32_t dst0 = xbase + (uint32_t)(stage * 16 * XS2 * 4);
        {                                              // 1024 float4 / 1024 thr
            int row = tid >> 6, c4 = tid & 63;
            CP_ASYNC16(dst0 + (uint32_t)((row * XS2 + c4 * 4) * 4),
                       xg + ((size_t)(b0 + row) * 512 + tt) * 256 + c4 * 4);
        }
        CP_COMMIT();
    };

    __syncthreads();
    issue_xg(dir ? 511 : 0, 0);
    issue_xg(dir ? 510 : 1, 1);
    CP_WAIT(1);

    for (int t = 0; t < 512; ++t) {
        const int tt  = dir ? (511 - t) : t;
        const int cur = t & 1, nxt = cur ^ 1;

        __syncthreads();   // single barrier per step

        if (t + 2 < 512) issue_xg(dir ? (509 - t) : (t + 2), (t + 2) % 3);

        const float* xs = sxg + (t % 3) * 16 * XS2;
        float acc[4];
        acc[0] = xs[r * XS2 + colA];
        acc[1] = xs[r * XS2 + colA + 64];
        acc[2] = xs[(r + 8) * XS2 + colA];
        acc[3] = xs[(r + 8) * XS2 + colA + 64];

        const uint32_t abase = hb32 + (uint32_t)(cur * 16 * HS2 * 2) + lmbase;
        #pragma unroll
        for (int kt = 0; kt < 4; ++kt) {
            uint32_t a0, a1, a2, a3;
            LDMATRIX_X4(a0, a1, a2, a3, abase + (uint32_t)(kt * 32));
            uint32_t afr[4] = {a0, a1, a2, a3};
            mma_fp16(acc, afr, bfr[kt]);
        }

        {
            float v0 = isState ? fmaxf(acc[0], 0.f) : sigf(acc[0]);
            float v1 = sigf(acc[1]);
            float v2 = isState ? fmaxf(acc[2], 0.f) : sigf(acc[2]);
            float v3 = sigf(acc[3]);
            float s0 = __shfl_xor_sync(0xffffffffu, v0, 1);
            float s1 = __shfl_xor_sync(0xffffffffu, v1, 1);
            float s2 = __shfl_xor_sync(0xffffffffu, v2, 1);
            float s3 = __shfl_xor_sync(0xffffffffu, v3, 1);
            if (isState) {
                float c0 = s1 * cst[0] + s0 * v0;
                float c1 = s3 * cst[1] + s2 * v2;
                cst[0] = c0; cst[1] = c1;
                float h0 = v1 * fmaxf(c0, 0.f);
                float h1 = v3 * fmaxf(c1, 0.f);
                hbufh[nxt * 16 * HS2 + r * HS2 + hj]       = __float2half(h0);
                hbufh[nxt * 16 * HS2 + (r + 8) * HS2 + hj] = __float2half(h1);
                if (t == 511) {
                    hout[(size_t)(b0 + r) * 128 + dir * 64 + hj]     = h0;
                    hout[(size_t)(b0 + r + 8) * 128 + dir * 64 + hj] = h1;
                }
            }
        }

        if (t + 2 < 512) { CP_WAIT(1); }
        else             { CP_WAIT(0); }
    }
}

// ------------------------------ heads ---------------------------------------
__global__ void __launch_bounds__(256)
head_kernel(const float* __restrict__ x64, const float* __restrict__ h2,
            const float* __restrict__ wz1, const float* __restrict__ bz1,
            const float* __restrict__ wz2, const float* __restrict__ bz2,
            const float* __restrict__ wt1, const float* __restrict__ bt1,
            const float* __restrict__ wt2, const float* __restrict__ bt2,
            float* __restrict__ out)
{
    const int b = threadIdx.x;
    float comb[192];
    #pragma unroll 4
    for (int k = 0; k < 64; ++k)  comb[k]      = x64[b*64 + k];
    #pragma unroll 4
    for (int k = 0; k < 128; ++k) comb[64 + k] = h2[b*128 + k];

    float z0 = bz1[0], z1 = bz1[1], t0 = bt1[0], t1 = bt1[1];
    #pragma unroll 4
    for (int k = 0; k < 192; ++k) {
        float v = comb[k];
        z0 += v * wz1[k*2 + 0]; z1 += v * wz1[k*2 + 1];
        t0 += v * wt1[k*2 + 0]; t1 += v * wt1[k*2 + 1];
    }
    out[b]       = fmaxf(z0,0.f)*wz2[0] + fmaxf(z1,0.f)*wz2[1] + bz2[0];
    out[256 + b] = fmaxf(t0,0.f)*wt2[0] + fmaxf(t1,0.f)*wt2[1] + bt2[0];
}

// ------------------------------ launcher ------------------------------------
extern "C" void kernel_launch(void* const* d_in, const int* in_sizes, int n_in,
                              void* d_out, int out_size)
{
    const int*   inputA = (const int*)  d_in[0];
    const float* inputB = (const float*)d_in[1];
    const float* emb = (const float*)d_in[2];
    const float *w1=(const float*)d_in[3],  *b1=(const float*)d_in[4];
    const float *w2=(const float*)d_in[5],  *b2=(const float*)d_in[6];
    const float *w3=(const float*)d_in[7],  *b3=(const float*)d_in[8];
    const float *k1f=(const float*)d_in[9],  *r1f=(const float*)d_in[10], *bb1f=(const float*)d_in[11];
    const float *k1b=(const float*)d_in[12], *r1b=(const float*)d_in[13], *bb1b=(const float*)d_in[14];
    const float *k2f=(const float*)d_in[15], *r2f=(const float*)d_in[16], *bb2f=(const float*)d_in[17];
    const float *k2b=(const float*)d_in[18], *r2b=(const float*)d_in[19], *bb2b=(const float*)d_in[20];
    const float *wz1=(const float*)d_in[21], *bz1=(const float*)d_in[22];
    const float *wz2=(const float*)d_in[23], *bz2=(const float*)d_in[24];
    const float *wt1=(const float*)d_in[25], *bt1=(const float*)d_in[26];
    const float *wt2=(const float*)d_in[27], *bt2=(const float*)d_in[28];
    float* out = (float*)d_out;

    float *xg1f, *xg1b, *xg2f, *xg2b, *x64, *h2;
    __half *xBhi, *xBlo, *Yhi, *Ylo, *wTh;
    cudaGetSymbolAddress((void**)&xg1f, g_xg1f);
    cudaGetSymbolAddress((void**)&xg1b, g_xg1b);
    cudaGetSymbolAddress((void**)&xg2f, g_xg2f);
    cudaGetSymbolAddress((void**)&xg2b, g_xg2b);
    cudaGetSymbolAddress((void**)&x64,  g_x64);
    cudaGetSymbolAddress((void**)&h2,   g_h2);
    cudaGetSymbolAddress((void**)&xBhi, g_xBhi);
    cudaGetSymbolAddress((void**)&xBlo, g_xBlo);
    cudaGetSymbolAddress((void**)&Yhi,  g_Yhi);
    cudaGetSymbolAddress((void**)&Ylo,  g_Ylo);
    cudaGetSymbolAddress((void**)&wTh,  g_wTh);

    __half *w1fh = wTh,            *w1bh = wTh + 65536;
    __half *w2fh = wTh + 2*65536,  *w2bh = wTh + 3*65536;

    const size_t sm1 = (size_t)(3*16*XS1*4 + 2*16*HS1*2 + 2*16*68*4 + 16);
    const size_t sm2 = (size_t)(3*16*XS2*4 + 2*16*HS2*2);

    static bool attr_done = false;
    if (!attr_done) {
        cudaFuncSetAttribute(gemm_fp16_kernel, cudaFuncAttributeMaxDynamicSharedMemorySize, 2*GSTAGE);
        cudaFuncSetAttribute(lstm1_mma_kernel, cudaFuncAttributeMaxDynamicSharedMemorySize, (int)sm1);
        cudaFuncSetAttribute(lstm2_mma_kernel, cudaFuncAttributeMaxDynamicSharedMemorySize, (int)sm2);
        attr_done = true;
    }

    prep_kernel<<<(SPLIT_N4 + 4*65536 + 255)/256, 256>>>(inputB, xBhi, xBlo,
                                                         k1f, k1b, k2f, k2b, wTh);  // 0
    const size_t gsm = 2*GSTAGE;
    gemm_fp16_kernel<<<dim3(1024,4), 256, gsm>>>(xBhi, xBlo, w1fh, bb1f, xg1f, BT, 512, 128); // 1
    gemm_fp16_kernel<<<dim3(1024,4), 256, gsm>>>(xBhi, xBlo, w1bh, bb1b, xg1b, BT, 512, 128); // 2

    lstm1_mma_kernel<<<dim3(32,2), 1024, sm1>>>(xg1f, xg1b, r1f, r1b, Yhi, Ylo);    // 3

    gemm_fp16_kernel<<<dim3(1024,2), 256, gsm>>>(Yhi, Ylo, w2fh, bb2f, xg2f, BT, 256, 256);   // 4
    gemm_fp16_kernel<<<dim3(1024,2), 256, gsm>>>(Yhi, Ylo, w2bh, bb2b, xg2b, BT, 256, 256);   // 5

    lstm2_mma_kernel<<<dim3(16,2), 1024, sm2>>>(xg2f, xg2b, r2f, r2b, h2);          // 6

    emb_mlp_kernel<<<256, 256>>>(inputA, emb, w1,b1, w2,b2, w3,b3, x64);            // 7
    head_kernel<<<1, 256>>>(x64, h2, wz1,bz1, wz2,bz2, wt1,bt1, wt2,bt2, out);      // 8
}

// round 16
// speedup vs baseline: 1.4069x; 1.2109x over previous
#include <cuda_runtime.h>
#include <cuda_fp16.h>
#include <cooperative_groups.h>
#include <cstdint>
namespace cg = cooperative_groups;

// ------------------------- scratch (device globals) -------------------------
#define BT (256*512)
__device__ float g_x64 [256*64];
__device__ float g_xg1f[(size_t)BT*512];
__device__ float g_xg1b[(size_t)BT*512];
__device__ float g_xg2f[(size_t)BT*256];
__device__ float g_xg2b[(size_t)BT*256];
__device__ float g_h2  [256*128];
__device__ __half g_xBhi[(size_t)BT*128];
__device__ __half g_xBlo[(size_t)BT*128];
__device__ __half g_Yhi [(size_t)BT*256];
__device__ __half g_Ylo [(size_t)BT*256];
__device__ __half g_wTh [4*65536];          // transposed weights [N,K], fp16

// ------------------------- small PTX helpers --------------------------------
__device__ __forceinline__ uint32_t smem_u32(const void* p) {
    uint32_t a;
    asm("{ .reg .u64 t; cvta.to.shared.u64 t, %1; cvt.u32.u64 %0, t; }" : "=r"(a) : "l"(p));
    return a;
}
__device__ __forceinline__ void mma_fp16(float* c, const uint32_t* a, const uint32_t* b) {
    asm volatile("mma.sync.aligned.m16n8k16.row.col.f32.f16.f16.f32 "
        "{%0,%1,%2,%3},{%4,%5,%6,%7},{%8,%9},{%0,%1,%2,%3};"
        : "+f"(c[0]), "+f"(c[1]), "+f"(c[2]), "+f"(c[3])
        : "r"(a[0]), "r"(a[1]), "r"(a[2]), "r"(a[3]), "r"(b[0]), "r"(b[1]));
}
#define LDMATRIX_X4(r0, r1, r2, r3, addr) \
    asm volatile("ldmatrix.sync.aligned.m8n8.x4.shared.b16 {%0,%1,%2,%3}, [%4];" \
        : "=r"(r0), "=r"(r1), "=r"(r2), "=r"(r3) : "r"(addr))
#define CP_ASYNC16(dst, src) asm volatile("cp.async.cg.shared.global [%0], [%1], 16;" :: "r"(dst), "l"(src))
#define CP_COMMIT()          asm volatile("cp.async.commit_group;" ::: "memory")
#define CP_WAIT(n)           asm volatile("cp.async.wait_group %0;" :: "n"(n) : "memory")

#define MBAR_INIT(mb, c) \
    asm volatile("mbarrier.init.shared.b64 [%0], %1;" :: "r"(mb), "r"(c) : "memory")
#define MBAR_ARRIVE_LOCAL(mb) \
    asm volatile("mbarrier.arrive.shared.b64 _, [%0];" :: "r"(mb) : "memory")
#define MBAR_ARRIVE_PEER(mb, peer) \
    asm volatile("{ .reg .b32 ra; mapa.shared::cluster.u32 ra, %0, %1;\n\t" \
                 "mbarrier.arrive.release.cluster.shared::cluster.b64 _, [ra]; }" \
                 :: "r"(mb), "r"(peer) : "memory")
#define MBAR_WAIT_CL(mb, ph) do { \
    uint32_t _m = (mb), _p = (ph), _d; \
    asm volatile("{ .reg .pred p; mbarrier.try_wait.parity.acquire.cluster.shared::cta.b64 p, [%1], %2, 0x989680; selp.b32 %0, 1, 0, p; }" \
        : "=r"(_d) : "r"(_m), "r"(_p) : "memory"); \
    if (!_d) { \
        asm volatile("{ .reg .pred P1;\n\tWL_%=: mbarrier.try_wait.parity.acquire.cluster.shared::cta.b64 P1, [%0], %1, 0x989680;\n\t@P1 bra.uni WD_%=;\n\tbra.uni WL_%=;\n\tWD_%=: }" \
            :: "r"(_m), "r"(_p) : "memory"); \
    } } while (0)

#define CLUSTER_ARRIVE() asm volatile("barrier.cluster.arrive.aligned;" ::: "memory")
#define CLUSTER_WAIT()   asm volatile("barrier.cluster.wait.aligned;" ::: "memory")

// fast sigmoid: 1/(1+2^(-x*log2e)) via ex2.approx + rcp.approx (~1e-6 rel err)
__device__ __forceinline__ float sigf(float x) {
    float r;
    asm("{ .reg .f32 t;\n\t"
        "mul.f32 t, %1, 0fBFB8AA3B;\n\t"
        "ex2.approx.f32 t, t;\n\t"
        "add.f32 t, t, 0f3F800000;\n\t"
        "rcp.approx.f32 %0, t; }"
        : "=f"(r) : "f"(x));
    return r;
}
__device__ __forceinline__ uint32_t pack_h2(__half a, __half b) {
    __half2 t = __halves2half2(a, b);
    return *(uint32_t*)&t;
}
__device__ __forceinline__ void split_h(float f, __half& hi, __half& lo) {
    hi = __float2half(f);
    lo = __float2half(f - __half2float(hi));
}

// --------- mega-prep: split inputB to fp16 hi/lo + transpose all weights ----
#define SPLIT_N4 (BT*128/4)
__global__ void __launch_bounds__(256)
prep_kernel(const float* __restrict__ inB, __half* __restrict__ hi, __half* __restrict__ lo,
            const float* __restrict__ k1f, const float* __restrict__ k1b,
            const float* __restrict__ k2f, const float* __restrict__ k2b,
            __half* __restrict__ wout)
{
    int idx = blockIdx.x * 256 + threadIdx.x;
    if (idx < SPLIT_N4) {
        float4 v = ((const float4*)inB)[idx];
        __half h0,h1,h2,h3,l0,l1,l2,l3;
        split_h(v.x,h0,l0); split_h(v.y,h1,l1);
        split_h(v.z,h2,l2); split_h(v.w,h3,l3);
        ((uint2*)hi)[idx] = make_uint2(pack_h2(h0,h1), pack_h2(h2,h3));
        ((uint2*)lo)[idx] = make_uint2(pack_h2(l0,l1), pack_h2(l2,l3));
    } else {
        int r = idx - SPLIT_N4;
        if (r < 4*65536) {
            int m = r >> 16, e = r & 65535;
            const float* src = (m == 0) ? k1f : (m == 1) ? k1b : (m == 2) ? k2f : k2b;
            int K = (m < 2) ? 128 : 256, N = (m < 2) ? 512 : 256;
            int n = e / K, k = e - n * K;
            wout[r] = __float2half(src[k * N + n]);
        }
    }
}

// ---- fp16 asymmetric 2-product GEMM + bias (unchanged) ---------------------
#define GSTAGE 30720
__global__ void __launch_bounds__(256, 2)
gemm_fp16_kernel(const __half* __restrict__ Ahi, const __half* __restrict__ Alo,
                 const __half* __restrict__ W,
                 const float* __restrict__ bias, float* __restrict__ C,
                 int M, int N, int K)
{
    extern __shared__ char smem[];
    const uint32_t smem_base = smem_u32(smem);
    const int tid = threadIdx.x;
    const int lane = tid & 31, wid = tid >> 5;
    const int m0 = blockIdx.x * 128, n0 = blockIdx.y * 128;
    const int wm = (wid >> 2) * 64, wn = (wid & 3) * 32;

    float acc[4][4][4];
    #pragma unroll
    for (int mt = 0; mt < 4; ++mt)
        #pragma unroll
        for (int nt = 0; nt < 4; ++nt)
            #pragma unroll
            for (int q = 0; q < 4; ++q) acc[mt][nt][q] = 0.f;

    const uint32_t lrow = (uint32_t)(lane & 15);
    const uint32_t lcol = (uint32_t)((lane >> 4) * 16);
    uint32_t offA[4], offB[2];
    #pragma unroll
    for (int mt = 0; mt < 4; ++mt)
        offA[mt] = (uint32_t)(wm + mt * 16 + lrow) * 80u + lcol;
    #pragma unroll
    for (int p = 0; p < 2; ++p)
        offB[p] = (uint32_t)(wn + p * 16 + lrow) * 80u + lcol;

    const int nch = K >> 5;
    auto issue = [&](int ch, int stage) {
        const int kc = ch << 5;
        const uint32_t st = smem_base + (uint32_t)stage * GSTAGE;
        #pragma unroll
        for (int i = 0; i < 2; ++i) {
            int idx = tid + i * 256;
            int row = idx >> 2, c = idx & 3;
            uint32_t soff = (uint32_t)(row * 80 + c * 16);
            size_t ga = (size_t)(m0 + row) * K + kc + c * 8;
            size_t gb = (size_t)(n0 + row) * K + kc + c * 8;
            CP_ASYNC16(st + soff,           Ahi + ga);
            CP_ASYNC16(st + 10240u + soff,  Alo + ga);
            CP_ASYNC16(st + 20480u + soff,  W   + gb);
        }
        CP_COMMIT();
    };

    issue(0, 0);
    for (int ch = 0; ch < nch; ++ch) {
        if (ch + 1 < nch) { issue(ch + 1, (ch + 1) & 1); CP_WAIT(1); }
        else             { CP_WAIT(0); }
        __syncthreads();

        const uint32_t stg = smem_base + (uint32_t)(ch & 1) * GSTAGE;
        #pragma unroll
        for (int kk = 0; kk < 2; ++kk) {
            const uint32_t kb = (uint32_t)(kk * 32);
            uint32_t bfr[4][2];
            #pragma unroll
            for (int p = 0; p < 2; ++p) {
                uint32_t r0, r1, r2, r3;
                LDMATRIX_X4(r0, r1, r2, r3, stg + 20480u + offB[p] + kb);
                bfr[2*p][0] = r0; bfr[2*p+1][0] = r1;
                bfr[2*p][1] = r2; bfr[2*p+1][1] = r3;
            }
            #pragma unroll
            for (int mt = 0; mt < 4; ++mt) {
                uint32_t ahi[4], alo[4];
                LDMATRIX_X4(ahi[0], ahi[1], ahi[2], ahi[3], stg + offA[mt] + kb);
                LDMATRIX_X4(alo[0], alo[1], alo[2], alo[3], stg + 10240u + offA[mt] + kb);
                #pragma unroll
                for (int nt = 0; nt < 4; ++nt) {
                    mma_fp16(acc[mt][nt], ahi, bfr[nt]);
                    mma_fp16(acc[mt][nt], alo, bfr[nt]);
                }
            }
        }
        __syncthreads();
    }

    #pragma unroll
    for (int mt = 0; mt < 4; ++mt) {
        int r = m0 + wm + mt * 16 + (lane >> 2);
        #pragma unroll
        for (int nt = 0; nt < 4; ++nt) {
            int col = n0 + wn + nt * 8 + (lane & 3) * 2;
            float b0 = __ldg(bias + col), b1 = __ldg(bias + col + 1);
            float2 v0 = make_float2(acc[mt][nt][0] + b0, acc[mt][nt][1] + b1);
            float2 v1 = make_float2(acc[mt][nt][2] + b0, acc[mt][nt][3] + b1);
            *(float2*)(C + (size_t)r * N + col)       = v0;
            *(float2*)(C + (size_t)(r + 8) * N + col) = v1;
        }
    }
}

// ------------------------- embedding MLP branch -----------------------------
__global__ void __launch_bounds__(256)
emb_mlp_kernel(const int* __restrict__ inputA, const float* __restrict__ emb,
               const float* __restrict__ w1, const float* __restrict__ b1,
               const float* __restrict__ w2, const float* __restrict__ b2,
               const float* __restrict__ w3, const float* __restrict__ b3,
               float* __restrict__ xout)
{
    __shared__ float x0[600], x1[256], x2[128];
    const int b = blockIdx.x, tid = threadIdx.x;
    for (int i = tid; i < 600; i += 256) {
        int la = i / 3, comp = i - la * 3;
        x0[i] = emb[inputA[b*200 + la]*3 + comp];
    }
    __syncthreads();
    {
        float acc = b1[tid];
        #pragma unroll 4
        for (int k = 0; k < 600; ++k) acc += x0[k] * w1[k*256 + tid];
        x1[tid] = fmaxf(acc, 0.f);
    }
    __syncthreads();
    if (tid < 128) {
        float acc = b2[tid];
        #pragma unroll 4
        for (int k = 0; k < 256; ++k) acc += x1[k] * w2[k*128 + tid];
        x2[tid] = fmaxf(acc, 0.f);
    }
    __syncthreads();
    if (tid < 64) {
        float acc = b3[tid];
        #pragma unroll 4
        for (int k = 0; k < 128; ++k) acc += x2[k] * w3[k*64 + tid];
        xout[b*64 + tid] = fmaxf(acc, 0.f);
    }
}

// ------ LSTM layer 1 (H=128) — R12 shape, batch tile 8 (half act/LDS/store) -
// 2-CTA cluster, 512 threads, 16 warps nt=2. hbuf rows 8-15 stay zero; only
// row r (0..7) is computed/stored. Grid (64,2) = 128 CTAs.
#define XS1 516
#define HS1 136
__global__ void __cluster_dims__(2,1,1) __launch_bounds__(512, 1)
lstm1_mma_kernel(const float* __restrict__ xg1f, const float* __restrict__ xg1b,
                 const float* __restrict__ r1f,  const float* __restrict__ r1b,
                 __half* __restrict__ Yhi, __half* __restrict__ Ylo)
{
    extern __shared__ char smraw[];
    float*  sxg   = (float*)smraw;                               // 3*8*XS1 f32
    __half* hbufh = (__half*)(smraw + 3*8*XS1*4);                // 2*16*HS1 f16
    float*  ybuf  = (float*)(smraw + 3*8*XS1*4 + 2*16*HS1*2);    // 2*8*68 f32
    const uint32_t mbar = smem_u32(smraw + 3*8*XS1*4 + 2*16*HS1*2 + 2*8*68*4);

    cg::cluster_group cl = cg::this_cluster();
    const int rank = cl.block_rank();
    const int dir  = blockIdx.y;
    const int b0   = (blockIdx.x >> 1) * 8;
    const int tid  = threadIdx.x;
    const int lane = tid & 31, w = tid >> 5;          // w in 0..15
    const int q    = lane & 3;
    const float* xg = dir ? xg1b : xg1f;
    const float* Wr = dir ? r1b : r1f;

    // fp16 weight fragments: warp covers 16 gate cols (nt = 0..1)
    uint32_t bfr[2][8][2];
    #pragma unroll
    for (int nt = 0; nt < 2; ++nt) {
        int n_local = w * 16 + nt * 8 + (lane >> 2);
        int G = (n_local & 3) * 128 + rank * 64 + (n_local >> 2);
        #pragma unroll
        for (int kt = 0; kt < 8; ++kt)
            #pragma unroll
            for (int p = 0; p < 2; ++p) {
                int k = kt * 16 + q * 2 + p * 8;
                bfr[nt][kt][p] = pack_h2(__float2half(Wr[k * 512 + G]),
                                         __float2half(Wr[(k + 1) * 512 + G]));
            }
    }

    for (int i = tid; i < 2 * 16 * HS1; i += 512) hbufh[i] = __float2half(0.f);
    if (tid == 0) MBAR_INIT(mbar, 2);

    const uint32_t hb32 = smem_u32(hbufh);
    const uint32_t xbase = smem_u32(sxg);
    const uint32_t lmbase = (uint32_t)(((lane & 15) * HS1 + ((lane >> 4) << 3)) * 2);
    const bool isState = (lane & 1);
    const int g0 = (q & 1) * 2;
    int colA[2], hj[2], al[2];
    #pragma unroll
    for (int nt = 0; nt < 2; ++nt) {
        int a_local = w * 4 + nt * 2 + (q >> 1);
        colA[nt] = g0 * 128 + rank * 64 + a_local;
        hj[nt]   = rank * 64 + a_local;
        al[nt]   = a_local;
    }
    const int r = lane >> 2;                          // batch row 0..7

    float cst[2] = {0.f, 0.f};                        // cell state per nt, row r

    auto issue_xg = [&](int tt, int stage) {
        const uint32_t dst0 = xbase + (uint32_t)(stage * 8 * XS1 * 4);
        #pragma unroll
        for (int i = 0; i < 2; ++i) {                 // 8 rows x 128 float4
            int idx = tid + i * 512;
            int row = idx >> 7, c4 = idx & 127;
            CP_ASYNC16(dst0 + (uint32_t)((row * XS1 + c4 * 4) * 4),
                       xg + ((size_t)(b0 + row) * 512 + tt) * 512 + c4 * 4);
        }
        CP_COMMIT();
    };
    auto store_Y = [&](int tprev) {
        if (tid < 128) {
            const float* yb = ybuf + (tprev & 1) * 8 * 68;
            int row = tid >> 4, c4 = tid & 15;        // 8 rows x 16 float4
            float4 v = *(const float4*)&yb[row * 68 + c4 * 4];
            int ttp = dir ? (511 - tprev) : tprev;
            size_t idx = ((size_t)(b0 + row) * 512 + ttp) * 256
                         + dir * 128 + rank * 64 + c4 * 4;
            __half h0,h1,h2,h3,l0,l1,l2,l3;
            split_h(v.x,h0,l0); split_h(v.y,h1,l1);
            split_h(v.z,h2,l2); split_h(v.w,h3,l3);
            *(uint2*)&Yhi[idx] = make_uint2(pack_h2(h0,h1), pack_h2(h2,h3));
            *(uint2*)&Ylo[idx] = make_uint2(pack_h2(l0,l1), pack_h2(l2,l3));
        }
    };

    __half* peer_h = (__half*)cl.map_shared_rank((void*)hbufh, rank ^ 1);
    __syncthreads();
    cl.sync();   // mbarrier init + hbuf zero visible cluster-wide

    issue_xg(dir ? 511 : 0, 0);
    issue_xg(dir ? 510 : 1, 1);
    CP_WAIT(1);  // stage 0 complete

    for (int t = 0; t < 512; ++t) {
        const int tt  = dir ? (511 - t) : t;
        const int cur = t & 1, nxt = cur ^ 1;

        __syncthreads();   // single barrier: publishes xg stage t, t-1 hbuf/ybuf

        if (t > 0) {
            if (tid == 0) {                     // release step t-1 stores to peer
                MBAR_ARRIVE_LOCAL(mbar);
                MBAR_ARRIVE_PEER(mbar, rank ^ 1);
            }
            store_Y(t - 1);
        }
        if (t + 2 < 512) issue_xg(dir ? (509 - t) : (t + 2), (t + 2) % 3);

        // acc init = xg for row r only; rows r+8 unused (hbuf rows 8-15 zero)
        const float* xs = sxg + (t % 3) * 8 * XS1;
        float acc[2][4];
        #pragma unroll
        for (int nt = 0; nt < 2; ++nt) {
            acc[nt][0] = xs[r * XS1 + colA[nt]];
            acc[nt][1] = xs[r * XS1 + colA[nt] + 128];
            acc[nt][2] = 0.f;
            acc[nt][3] = 0.f;
        }

        if (t > 0) MBAR_WAIT_CL(mbar, (t - 1) & 1);

        const uint32_t abase = hb32 + (uint32_t)(cur * 16 * HS1 * 2) + lmbase;
        #pragma unroll
        for (int kt = 0; kt < 8; ++kt) {
            uint32_t a0, a1, a2, a3;
            LDMATRIX_X4(a0, a1, a2, a3, abase + (uint32_t)(kt * 32));
            uint32_t afr[4] = {a0, a1, a2, a3};
            #pragma unroll
            for (int nt = 0; nt < 2; ++nt)
                mma_fp16(acc[nt], afr, bfr[nt][kt]);
        }

        float* yb = ybuf + (t & 1) * 8 * 68;
        #pragma unroll
        for (int nt = 0; nt < 2; ++nt) {
            float v0 = isState ? fmaxf(acc[nt][0], 0.f) : sigf(acc[nt][0]);
            float v1 = sigf(acc[nt][1]);
            float s0 = __shfl_xor_sync(0xffffffffu, v0, 1);
            float s1 = __shfl_xor_sync(0xffffffffu, v1, 1);
            if (isState) {
                float c0 = s1 * cst[nt] + s0 * v0;
                cst[nt] = c0;
                float h0 = v1 * fmaxf(c0, 0.f);
                __half h0h = __float2half(h0);
                int o0 = nxt * 16 * HS1 + r * HS1 + hj[nt];
                hbufh[o0] = h0h;
                peer_h[o0] = h0h;
                yb[r * 68 + al[nt]] = h0;
            }
        }

        if (t + 2 < 512) { CP_WAIT(1); }
        else             { CP_WAIT(0); }
    }

    // keep CTA alive until peer's final-step DSMEM writes complete
    __syncthreads();
    CLUSTER_ARRIVE();
    store_Y(511);
    CLUSTER_WAIT();
}

// ------ LSTM layer 2 (H=64) — R12 shape, batch tile 8, single CTA -----------
#define XS2 260
#define HS2 72
__global__ void __launch_bounds__(512, 1)
lstm2_mma_kernel(const float* __restrict__ xg2f, const float* __restrict__ xg2b,
                 const float* __restrict__ r2f,  const float* __restrict__ r2b,
                 float* __restrict__ hout)
{
    extern __shared__ char smraw[];
    float*  sxg   = (float*)smraw;                     // 3*8*XS2 f32
    __half* hbufh = (__half*)(smraw + 3*8*XS2*4);      // 2*16*HS2 f16

    const int dir = blockIdx.y;
    const int b0  = blockIdx.x * 8;
    const int tid = threadIdx.x;
    const int lane = tid & 31, w = tid >> 5;           // 0..15
    const int q = lane & 3;
    const float* xg = dir ? xg2b : xg2f;
    const float* Wr = dir ? r2b : r2f;

    uint32_t bfr[2][4][2];
    #pragma unroll
    for (int nt = 0; nt < 2; ++nt) {
        int n_local = w * 16 + nt * 8 + (lane >> 2);
        int G = (n_local & 3) * 64 + (n_local >> 2);
        #pragma unroll
        for (int kt = 0; kt < 4; ++kt)
            #pragma unroll
            for (int p = 0; p < 2; ++p) {
                int k = kt * 16 + q * 2 + p * 8;
                bfr[nt][kt][p] = pack_h2(__float2half(Wr[k * 256 + G]),
                                         __float2half(Wr[(k + 1) * 256 + G]));
            }
    }

    for (int i = tid; i < 2 * 16 * HS2; i += 512) hbufh[i] = __float2half(0.f);

    const uint32_t hb32 = smem_u32(hbufh);
    const uint32_t xbase = smem_u32(sxg);
    const uint32_t lmbase = (uint32_t)(((lane & 15) * HS2 + ((lane >> 4) << 3)) * 2);
    const bool isState = (lane & 1);
    const int g0 = (q & 1) * 2;
    int colA[2], hj[2];
    #pragma unroll
    for (int nt = 0; nt < 2; ++nt) {
        int a_local = w * 4 + nt * 2 + (q >> 1);
        colA[nt] = g0 * 64 + a_local;
        hj[nt]   = a_local;
    }
    const int r = lane >> 2;

    float cst[2] = {0.f, 0.f};

    auto issue_xg = [&](int tt, int stage) {
        const uint32_t dst0 = xbase + (uint32_t)(stage * 8 * XS2 * 4);
        if (tid < 512) {                               // 8 rows x 64 float4
            int row = tid >> 6, c4 = tid & 63;
            CP_ASYNC16(dst0 + (uint32_t)((row * XS2 + c4 * 4) * 4),
                       xg + ((size_t)(b0 + row) * 512 + tt) * 256 + c4 * 4);
        }
        CP_COMMIT();
    };

    __syncthreads();
    issue_xg(dir ? 511 : 0, 0);
    issue_xg(dir ? 510 : 1, 1);
    CP_WAIT(1);

    for (int t = 0; t < 512; ++t) {
        const int tt  = dir ? (511 - t) : t;
        const int cur = t & 1, nxt = cur ^ 1;

        __syncthreads();   // single barrier per step

        if (t + 2 < 512) issue_xg(dir ? (509 - t) : (t + 2), (t + 2) % 3);

        const float* xs = sxg + (t % 3) * 8 * XS2;
        float acc[2][4];
        #pragma unroll
        for (int nt = 0; nt < 2; ++nt) {
            acc[nt][0] = xs[r * XS2 + colA[nt]];
            acc[nt][1] = xs[r * XS2 + colA[nt] + 64];
            acc[nt][2] = 0.f;
            acc[nt][3] = 0.f;
        }

        const uint32_t abase = hb32 + (uint32_t)(cur * 16 * HS2 * 2) + lmbase;
        #pragma unroll
        for (int kt = 0; kt < 4; ++kt) {
            uint32_t a0, a1, a2, a3;
            LDMATRIX_X4(a0, a1, a2, a3, abase + (uint32_t)(kt * 32));
            uint32_t afr[4] = {a0, a1, a2, a3};
            #pragma unroll
            for (int nt = 0; nt < 2; ++nt)
                mma_fp16(acc[nt], afr, bfr[nt][kt]);
        }

        #pragma unroll
        for (int nt = 0; nt < 2; ++nt) {
            float v0 = isState ? fmaxf(acc[nt][0], 0.f) : sigf(acc[nt][0]);
            float v1 = sigf(acc[nt][1]);
            float s0 = __shfl_xor_sync(0xffffffffu, v0, 1);
            float s1 = __shfl_xor_sync(0xffffffffu, v1, 1);
            if (isState) {
                float c0 = s1 * cst[nt] + s0 * v0;
                cst[nt] = c0;
                float h0 = v1 * fmaxf(c0, 0.f);
                hbufh[nxt * 16 * HS2 + r * HS2 + hj[nt]] = __float2half(h0);
                if (t == 511)
                    hout[(size_t)(b0 + r) * 128 + dir * 64 + hj[nt]] = h0;
            }
        }

        if (t + 2 < 512) { CP_WAIT(1); }
        else             { CP_WAIT(0); }
    }
}

// ------------------------------ heads ---------------------------------------
__global__ void __launch_bounds__(256)
head_kernel(const float* __restrict__ x64, const float* __restrict__ h2,
            const float* __restrict__ wz1, const float* __restrict__ bz1,
            const float* __restrict__ wz2, const float* __restrict__ bz2,
            const float* __restrict__ wt1, const float* __restrict__ bt1,
            const float* __restrict__ wt2, const float* __restrict__ bt2,
            float* __restrict__ out)
{
    const int b = threadIdx.x;
    float comb[192];
    #pragma unroll 4
    for (int k = 0; k < 64; ++k)  comb[k]      = x64[b*64 + k];
    #pragma unroll 4
    for (int k = 0; k < 128; ++k) comb[64 + k] = h2[b*128 + k];

    float z0 = bz1[0], z1 = bz1[1], t0 = bt1[0], t1 = bt1[1];
    #pragma unroll 4
    for (int k = 0; k < 192; ++k) {
        float v = comb[k];
        z0 += v * wz1[k*2 + 0]; z1 += v * wz1[k*2 + 1];
        t0 += v * wt1[k*2 + 0]; t1 += v * wt1[k*2 + 1];
    }
    out[b]       = fmaxf(z0,0.f)*wz2[0] + fmaxf(z1,0.f)*wz2[1] + bz2[0];
    out[256 + b] = fmaxf(t0,0.f)*wt2[0] + fmaxf(t1,0.f)*wt2[1] + bt2[0];
}

// ------------------------------ launcher ------------------------------------
extern "C" void kernel_launch(void* const* d_in, const int* in_sizes, int n_in,
                              void* d_out, int out_size)
{
    const int*   inputA = (const int*)  d_in[0];
    const float* inputB = (const float*)d_in[1];
    const float* emb = (const float*)d_in[2];
    const float *w1=(const float*)d_in[3],  *b1=(const float*)d_in[4];
    const float *w2=(const float*)d_in[5],  *b2=(const float*)d_in[6];
    const float *w3=(const float*)d_in[7],  *b3=(const float*)d_in[8];
    const float *k1f=(const float*)d_in[9],  *r1f=(const float*)d_in[10], *bb1f=(const float*)d_in[11];
    const float *k1b=(const float*)d_in[12], *r1b=(const float*)d_in[13], *bb1b=(const float*)d_in[14];
    const float *k2f=(const float*)d_in[15], *r2f=(const float*)d_in[16], *bb2f=(const float*)d_in[17];
    const float *k2b=(const float*)d_in[18], *r2b=(const float*)d_in[19], *bb2b=(const float*)d_in[20];
    const float *wz1=(const float*)d_in[21], *bz1=(const float*)d_in[22];
    const float *wz2=(const float*)d_in[23], *bz2=(const float*)d_in[24];
    const float *wt1=(const float*)d_in[25], *bt1=(const float*)d_in[26];
    const float *wt2=(const float*)d_in[27], *bt2=(const float*)d_in[28];
    float* out = (float*)d_out;

    float *xg1f, *xg1b, *xg2f, *xg2b, *x64, *h2;
    __half *xBhi, *xBlo, *Yhi, *Ylo, *wTh;
    cudaGetSymbolAddress((void**)&xg1f, g_xg1f);
    cudaGetSymbolAddress((void**)&xg1b, g_xg1b);
    cudaGetSymbolAddress((void**)&xg2f, g_xg2f);
    cudaGetSymbolAddress((void**)&xg2b, g_xg2b);
    cudaGetSymbolAddress((void**)&x64,  g_x64);
    cudaGetSymbolAddress((void**)&h2,   g_h2);
    cudaGetSymbolAddress((void**)&xBhi, g_xBhi);
    cudaGetSymbolAddress((void**)&xBlo, g_xBlo);
    cudaGetSymbolAddress((void**)&Yhi,  g_Yhi);
    cudaGetSymbolAddress((void**)&Ylo,  g_Ylo);
    cudaGetSymbolAddress((void**)&wTh,  g_wTh);

    __half *w1fh = wTh,            *w1bh = wTh + 65536;
    __half *w2fh = wTh + 2*65536,  *w2bh = wTh + 3*65536;

    const size_t sm1 = (size_t)(3*8*XS1*4 + 2*16*HS1*2 + 2*8*68*4 + 16);
    const size_t sm2 = (size_t)(3*8*XS2*4 + 2*16*HS2*2);

    static bool attr_done = false;
    if (!attr_done) {
        cudaFuncSetAttribute(gemm_fp16_kernel, cudaFuncAttributeMaxDynamicSharedMemorySize, 2*GSTAGE);
        cudaFuncSetAttribute(lstm1_mma_kernel, cudaFuncAttributeMaxDynamicSharedMemorySize, (int)sm1);
        cudaFuncSetAttribute(lstm2_mma_kernel, cudaFuncAttributeMaxDynamicSharedMemorySize, (int)sm2);
        attr_done = true;
    }

    prep_kernel<<<(SPLIT_N4 + 4*65536 + 255)/256, 256>>>(inputB, xBhi, xBlo,
                                                         k1f, k1b, k2f, k2b, wTh);  // 0
    const size_t gsm = 2*GSTAGE;
    gemm_fp16_kernel<<<dim3(1024,4), 256, gsm>>>(xBhi, xBlo, w1fh, bb1f, xg1f, BT, 512, 128); // 1
    gemm_fp16_kernel<<<dim3(1024,4), 256, gsm>>>(xBhi, xBlo, w1bh, bb1b, xg1b, BT, 512, 128); // 2

    lstm1_mma_kernel<<<dim3(64,2), 512, sm1>>>(xg1f, xg1b, r1f, r1b, Yhi, Ylo);     // 3

    gemm_fp16_kernel<<<dim3(1024,2), 256, gsm>>>(Yhi, Ylo, w2fh, bb2f, xg2f, BT, 256, 256);   // 4
    gemm_fp16_kernel<<<dim3(1024,2), 256, gsm>>>(Yhi, Ylo, w2bh, bb2b, xg2b, BT, 256, 256);   // 5

    lstm2_mma_kernel<<<dim3(32,2), 512, sm2>>>(xg2f, xg2b, r2f, r2b, h2);           // 6

    emb_mlp_kernel<<<256, 256>>>(inputA, emb, w1,b1, w2,b2, w3,b3, x64);            // 7
    head_kernel<<<1, 256>>>(x64, h2, wz1,bz1, wz2,bz2, wt1,bt1, wt2,bt2, out);      // 8
}

// round 17
// speedup vs baseline: 1.4340x; 1.0193x over previous
#include <cuda_runtime.h>
#include <cuda_fp16.h>
#include <cooperative_groups.h>
#include <cstdint>
namespace cg = cooperative_groups;

// ------------------------- scratch (device globals) -------------------------
#define BT (256*512)
__device__ float g_x64 [256*64];
__device__ float g_xg1f[(size_t)BT*512];
__device__ float g_xg1b[(size_t)BT*512];
__device__ float g_xg2f[(size_t)BT*256];
__device__ float g_xg2b[(size_t)BT*256];
__device__ float g_h2  [256*128];
__device__ __half g_xBhi[(size_t)BT*128];
__device__ __half g_xBlo[(size_t)BT*128];
__device__ __half g_Yhi [(size_t)BT*256];
__device__ __half g_Ylo [(size_t)BT*256];
__device__ __half g_wTh [4*65536];          // transposed weights [N,K], fp16

// ------------------------- small PTX helpers --------------------------------
__device__ __forceinline__ uint32_t smem_u32(const void* p) {
    uint32_t a;
    asm("{ .reg .u64 t; cvta.to.shared.u64 t, %1; cvt.u32.u64 %0, t; }" : "=r"(a) : "l"(p));
    return a;
}
__device__ __forceinline__ void mma_fp16(float* c, const uint32_t* a, const uint32_t* b) {
    asm volatile("mma.sync.aligned.m16n8k16.row.col.f32.f16.f16.f32 "
        "{%0,%1,%2,%3},{%4,%5,%6,%7},{%8,%9},{%0,%1,%2,%3};"
        : "+f"(c[0]), "+f"(c[1]), "+f"(c[2]), "+f"(c[3])
        : "r"(a[0]), "r"(a[1]), "r"(a[2]), "r"(a[3]), "r"(b[0]), "r"(b[1]));
}
#define LDMATRIX_X4(r0, r1, r2, r3, addr) \
    asm volatile("ldmatrix.sync.aligned.m8n8.x4.shared.b16 {%0,%1,%2,%3}, [%4];" \
        : "=r"(r0), "=r"(r1), "=r"(r2), "=r"(r3) : "r"(addr))
#define LDMATRIX_X2(r0, r1, addr) \
    asm volatile("ldmatrix.sync.aligned.m8n8.x2.shared.b16 {%0,%1}, [%2];" \
        : "=r"(r0), "=r"(r1) : "r"(addr))
#define CP_ASYNC16(dst, src) asm volatile("cp.async.cg.shared.global [%0], [%1], 16;" :: "r"(dst), "l"(src))
#define CP_COMMIT()          asm volatile("cp.async.commit_group;" ::: "memory")
#define CP_WAIT(n)           asm volatile("cp.async.wait_group %0;" :: "n"(n) : "memory")

#define MBAR_INIT(mb, c) \
    asm volatile("mbarrier.init.shared.b64 [%0], %1;" :: "r"(mb), "r"(c) : "memory")
#define MBAR_ARRIVE_LOCAL(mb) \
    asm volatile("mbarrier.arrive.shared.b64 _, [%0];" :: "r"(mb) : "memory")
#define MBAR_ARRIVE_PEER(mb, peer) \
    asm volatile("{ .reg .b32 ra; mapa.shared::cluster.u32 ra, %0, %1;\n\t" \
                 "mbarrier.arrive.release.cluster.shared::cluster.b64 _, [ra]; }" \
                 :: "r"(mb), "r"(peer) : "memory")
#define MBAR_WAIT_CL(mb, ph) do { \
    uint32_t _m = (mb), _p = (ph), _d; \
    asm volatile("{ .reg .pred p; mbarrier.try_wait.parity.acquire.cluster.shared::cta.b64 p, [%1], %2, 0x989680; selp.b32 %0, 1, 0, p; }" \
        : "=r"(_d) : "r"(_m), "r"(_p) : "memory"); \
    if (!_d) { \
        asm volatile("{ .reg .pred P1;\n\tWL_%=: mbarrier.try_wait.parity.acquire.cluster.shared::cta.b64 P1, [%0], %1, 0x989680;\n\t@P1 bra.uni WD_%=;\n\tbra.uni WL_%=;\n\tWD_%=: }" \
            :: "r"(_m), "r"(_p) : "memory"); \
    } } while (0)

#define CLUSTER_ARRIVE() asm volatile("barrier.cluster.arrive.aligned;" ::: "memory")
#define CLUSTER_WAIT()   asm volatile("barrier.cluster.wait.aligned;" ::: "memory")

// fast sigmoid: 1/(1+2^(-x*log2e)) via ex2.approx + rcp.approx (~1e-6 rel err)
__device__ __forceinline__ float sigf(float x) {
    float r;
    asm("{ .reg .f32 t;\n\t"
        "mul.f32 t, %1, 0fBFB8AA3B;\n\t"
        "ex2.approx.f32 t, t;\n\t"
        "add.f32 t, t, 0f3F800000;\n\t"
        "rcp.approx.f32 %0, t; }"
        : "=f"(r) : "f"(x));
    return r;
}
__device__ __forceinline__ uint32_t pack_h2(__half a, __half b) {
    __half2 t = __halves2half2(a, b);
    return *(uint32_t*)&t;
}
__device__ __forceinline__ void split_h(float f, __half& hi, __half& lo) {
    hi = __float2half(f);
    lo = __float2half(f - __half2float(hi));
}

// --------- mega-prep: split inputB to fp16 hi/lo + transpose all weights ----
#define SPLIT_N4 (BT*128/4)
__global__ void __launch_bounds__(256)
prep_kernel(const float* __restrict__ inB, __half* __restrict__ hi, __half* __restrict__ lo,
            const float* __restrict__ k1f, const float* __restrict__ k1b,
            const float* __restrict__ k2f, const float* __restrict__ k2b,
            __half* __restrict__ wout)
{
    int idx = blockIdx.x * 256 + threadIdx.x;
    if (idx < SPLIT_N4) {
        float4 v = ((const float4*)inB)[idx];
        __half h0,h1,h2,h3,l0,l1,l2,l3;
        split_h(v.x,h0,l0); split_h(v.y,h1,l1);
        split_h(v.z,h2,l2); split_h(v.w,h3,l3);
        ((uint2*)hi)[idx] = make_uint2(pack_h2(h0,h1), pack_h2(h2,h3));
        ((uint2*)lo)[idx] = make_uint2(pack_h2(l0,l1), pack_h2(l2,l3));
    } else {
        int r = idx - SPLIT_N4;
        if (r < 4*65536) {
            int m = r >> 16, e = r & 65535;
            const float* src = (m == 0) ? k1f : (m == 1) ? k1b : (m == 2) ? k2f : k2b;
            int K = (m < 2) ? 128 : 256, N = (m < 2) ? 512 : 256;
            int n = e / K, k = e - n * K;
            wout[r] = __float2half(src[k * N + n]);
        }
    }
}

// ---- fp16 asymmetric 2-product GEMM + bias (unchanged) ---------------------
#define GSTAGE 30720
__global__ void __launch_bounds__(256, 2)
gemm_fp16_kernel(const __half* __restrict__ Ahi, const __half* __restrict__ Alo,
                 const __half* __restrict__ W,
                 const float* __restrict__ bias, float* __restrict__ C,
                 int M, int N, int K)
{
    extern __shared__ char smem[];
    const uint32_t smem_base = smem_u32(smem);
    const int tid = threadIdx.x;
    const int lane = tid & 31, wid = tid >> 5;
    const int m0 = blockIdx.x * 128, n0 = blockIdx.y * 128;
    const int wm = (wid >> 2) * 64, wn = (wid & 3) * 32;

    float acc[4][4][4];
    #pragma unroll
    for (int mt = 0; mt < 4; ++mt)
        #pragma unroll
        for (int nt = 0; nt < 4; ++nt)
            #pragma unroll
            for (int q = 0; q < 4; ++q) acc[mt][nt][q] = 0.f;

    const uint32_t lrow = (uint32_t)(lane & 15);
    const uint32_t lcol = (uint32_t)((lane >> 4) * 16);
    uint32_t offA[4], offB[2];
    #pragma unroll
    for (int mt = 0; mt < 4; ++mt)
        offA[mt] = (uint32_t)(wm + mt * 16 + lrow) * 80u + lcol;
    #pragma unroll
    for (int p = 0; p < 2; ++p)
        offB[p] = (uint32_t)(wn + p * 16 + lrow) * 80u + lcol;

    const int nch = K >> 5;
    auto issue = [&](int ch, int stage) {
        const int kc = ch << 5;
        const uint32_t st = smem_base + (uint32_t)stage * GSTAGE;
        #pragma unroll
        for (int i = 0; i < 2; ++i) {
            int idx = tid + i * 256;
            int row = idx >> 2, c = idx & 3;
            uint32_t soff = (uint32_t)(row * 80 + c * 16);
            size_t ga = (size_t)(m0 + row) * K + kc + c * 8;
            size_t gb = (size_t)(n0 + row) * K + kc + c * 8;
            CP_ASYNC16(st + soff,           Ahi + ga);
            CP_ASYNC16(st + 10240u + soff,  Alo + ga);
            CP_ASYNC16(st + 20480u + soff,  W   + gb);
        }
        CP_COMMIT();
    };

    issue(0, 0);
    for (int ch = 0; ch < nch; ++ch) {
        if (ch + 1 < nch) { issue(ch + 1, (ch + 1) & 1); CP_WAIT(1); }
        else             { CP_WAIT(0); }
        __syncthreads();

        const uint32_t stg = smem_base + (uint32_t)(ch & 1) * GSTAGE;
        #pragma unroll
        for (int kk = 0; kk < 2; ++kk) {
            const uint32_t kb = (uint32_t)(kk * 32);
            uint32_t bfr[4][2];
            #pragma unroll
            for (int p = 0; p < 2; ++p) {
                uint32_t r0, r1, r2, r3;
                LDMATRIX_X4(r0, r1, r2, r3, stg + 20480u + offB[p] + kb);
                bfr[2*p][0] = r0; bfr[2*p+1][0] = r1;
                bfr[2*p][1] = r2; bfr[2*p+1][1] = r3;
            }
            #pragma unroll
            for (int mt = 0; mt < 4; ++mt) {
                uint32_t ahi[4], alo[4];
                LDMATRIX_X4(ahi[0], ahi[1], ahi[2], ahi[3], stg + offA[mt] + kb);
                LDMATRIX_X4(alo[0], alo[1], alo[2], alo[3], stg + 10240u + offA[mt] + kb);
                #pragma unroll
                for (int nt = 0; nt < 4; ++nt) {
                    mma_fp16(acc[mt][nt], ahi, bfr[nt]);
                    mma_fp16(acc[mt][nt], alo, bfr[nt]);
                }
            }
        }
        __syncthreads();
    }

    #pragma unroll
    for (int mt = 0; mt < 4; ++mt) {
        int r = m0 + wm + mt * 16 + (lane >> 2);
        #pragma unroll
        for (int nt = 0; nt < 4; ++nt) {
            int col = n0 + wn + nt * 8 + (lane & 3) * 2;
            float b0 = __ldg(bias + col), b1 = __ldg(bias + col + 1);
            float2 v0 = make_float2(acc[mt][nt][0] + b0, acc[mt][nt][1] + b1);
            float2 v1 = make_float2(acc[mt][nt][2] + b0, acc[mt][nt][3] + b1);
            *(float2*)(C + (size_t)r * N + col)       = v0;
            *(float2*)(C + (size_t)(r + 8) * N + col) = v1;
        }
    }
}

// ------------------------- embedding MLP branch -----------------------------
__global__ void __launch_bounds__(256)
emb_mlp_kernel(const int* __restrict__ inputA, const float* __restrict__ emb,
               const float* __restrict__ w1, const float* __restrict__ b1,
               const float* __restrict__ w2, const float* __restrict__ b2,
               const float* __restrict__ w3, const float* __restrict__ b3,
               float* __restrict__ xout)
{
    __shared__ float x0[600], x1[256], x2[128];
    const int b = blockIdx.x, tid = threadIdx.x;
    for (int i = tid; i < 600; i += 256) {
        int la = i / 3, comp = i - la * 3;
        x0[i] = emb[inputA[b*200 + la]*3 + comp];
    }
    __syncthreads();
    {
        float acc = b1[tid];
        #pragma unroll 4
        for (int k = 0; k < 600; ++k) acc += x0[k] * w1[k*256 + tid];
        x1[tid] = fmaxf(acc, 0.f);
    }
    __syncthreads();
    if (tid < 128) {
        float acc = b2[tid];
        #pragma unroll 4
        for (int k = 0; k < 256; ++k) acc += x1[k] * w2[k*128 + tid];
        x2[tid] = fmaxf(acc, 0.f);
    }
    __syncthreads();
    if (tid < 64) {
        float acc = b3[tid];
        #pragma unroll 4
        for (int k = 0; k < 128; ++k) acc += x2[k] * w3[k*64 + tid];
        xout[b*64 + tid] = fmaxf(acc, 0.f);
    }
}

// ------ LSTM layer 1 (H=128) — R15 + packed xg staging + ldmatrix.x2 --------
// 2-CTA cluster, 512 threads, 16 warps nt=2, batch tile 8.
// xg staged PACKED: only this rank's 256 cols (g*64+a layout, stride 260).
// A-fragments via ldmatrix.x2 (rows 0-7 only; rows 8-15 are constant zeros).
#define XS1P 260
#define HS1 136
__global__ void __cluster_dims__(2,1,1) __launch_bounds__(512, 1)
lstm1_mma_kernel(const float* __restrict__ xg1f, const float* __restrict__ xg1b,
                 const float* __restrict__ r1f,  const float* __restrict__ r1b,
                 __half* __restrict__ Yhi, __half* __restrict__ Ylo)
{
    extern __shared__ char smraw[];
    float*  sxg   = (float*)smraw;                               // 3*8*XS1P f32
    __half* hbufh = (__half*)(smraw + 3*8*XS1P*4);               // 2*8*HS1 f16
    float*  ybuf  = (float*)(smraw + 3*8*XS1P*4 + 2*8*HS1*2);    // 2*8*68 f32
    const uint32_t mbar = smem_u32(smraw + 3*8*XS1P*4 + 2*8*HS1*2 + 2*8*68*4);

    cg::cluster_group cl = cg::this_cluster();
    const int rank = cl.block_rank();
    const int dir  = blockIdx.y;
    const int b0   = (blockIdx.x >> 1) * 8;
    const int tid  = threadIdx.x;
    const int lane = tid & 31, w = tid >> 5;          // w in 0..15
    const int q    = lane & 3;
    const float* xg = dir ? xg1b : xg1f;
    const float* Wr = dir ? r1b : r1f;

    // fp16 weight fragments: warp covers 16 gate cols (nt = 0..1)
    uint32_t bfr[2][8][2];
    #pragma unroll
    for (int nt = 0; nt < 2; ++nt) {
        int n_local = w * 16 + nt * 8 + (lane >> 2);
        int G = (n_local & 3) * 128 + rank * 64 + (n_local >> 2);
        #pragma unroll
        for (int kt = 0; kt < 8; ++kt)
            #pragma unroll
            for (int p = 0; p < 2; ++p) {
                int k = kt * 16 + q * 2 + p * 8;
                bfr[nt][kt][p] = pack_h2(__float2half(Wr[k * 512 + G]),
                                         __float2half(Wr[(k + 1) * 512 + G]));
            }
    }

    for (int i = tid; i < 2 * 8 * HS1; i += 512) hbufh[i] = __float2half(0.f);
    if (tid == 0) MBAR_INIT(mbar, 2);

    const uint32_t hb32 = smem_u32(hbufh);
    const uint32_t xbase = smem_u32(sxg);
    // ldmatrix.x2 addressing: lanes 0-7 -> rows 0-7 k0, lanes 8-15 -> rows 0-7 k8
    const uint32_t lmbase = (uint32_t)(((lane & 7) * HS1 + (((lane >> 3) & 1) << 3)) * 2);
    const bool isState = (lane & 1);
    int colA[2], hj[2], al[2];
    #pragma unroll
    for (int nt = 0; nt < 2; ++nt) {
        int a_local = w * 4 + nt * 2 + (q >> 1);
        colA[nt] = (q & 1) * 128 + a_local;           // packed: g0*64 = (q&1)*128
        hj[nt]   = rank * 64 + a_local;
        al[nt]   = a_local;
    }
    const int r = lane >> 2;                          // batch row 0..7

    float cst[2] = {0.f, 0.f};

    // packed xg stage: 8 rows x 256 cols (this rank's), 512 float4 = 1/thread
    auto issue_xg = [&](int tt, int stage) {
        const uint32_t dst0 = xbase + (uint32_t)(stage * 8 * XS1P * 4);
        int row = tid >> 6, c4 = tid & 63;
        int g = c4 >> 4, a4 = c4 & 15;
        CP_ASYNC16(dst0 + (uint32_t)((row * XS1P + c4 * 4) * 4),
                   xg + ((size_t)(b0 + row) * 512 + tt) * 512
                      + g * 128 + rank * 64 + a4 * 4);
        CP_COMMIT();
    };
    auto store_Y = [&](int tprev) {
        if (tid < 128) {
            const float* yb = ybuf + (tprev & 1) * 8 * 68;
            int row = tid >> 4, c4 = tid & 15;
            float4 v = *(const float4*)&yb[row * 68 + c4 * 4];
            int ttp = dir ? (511 - tprev) : tprev;
            size_t idx = ((size_t)(b0 + row) * 512 + ttp) * 256
                         + dir * 128 + rank * 64 + c4 * 4;
            __half h0,h1,h2,h3,l0,l1,l2,l3;
            split_h(v.x,h0,l0); split_h(v.y,h1,l1);
            split_h(v.z,h2,l2); split_h(v.w,h3,l3);
            *(uint2*)&Yhi[idx] = make_uint2(pack_h2(h0,h1), pack_h2(h2,h3));
            *(uint2*)&Ylo[idx] = make_uint2(pack_h2(l0,l1), pack_h2(l2,l3));
        }
    };

    __half* peer_h = (__half*)cl.map_shared_rank((void*)hbufh, rank ^ 1);
    __syncthreads();
    cl.sync();   // mbarrier init + hbuf zero visible cluster-wide

    issue_xg(dir ? 511 : 0, 0);
    issue_xg(dir ? 510 : 1, 1);
    CP_WAIT(1);  // stage 0 complete

    for (int t = 0; t < 512; ++t) {
        const int tt  = dir ? (511 - t) : t;
        const int cur = t & 1, nxt = cur ^ 1;

        __syncthreads();   // single barrier: publishes xg stage t, t-1 hbuf/ybuf

        if (t > 0) {
            if (tid == 0) {                     // release step t-1 stores to peer
                MBAR_ARRIVE_LOCAL(mbar);
                MBAR_ARRIVE_PEER(mbar, rank ^ 1);
            }
            store_Y(t - 1);
        }
        if (t + 2 < 512) issue_xg(dir ? (509 - t) : (t + 2), (t + 2) % 3);

        // acc init = xg (packed layout) for row r only
        const float* xs = sxg + (t % 3) * 8 * XS1P;
        float acc[2][4];
        #pragma unroll
        for (int nt = 0; nt < 2; ++nt) {
            acc[nt][0] = xs[r * XS1P + colA[nt]];
            acc[nt][1] = xs[r * XS1P + colA[nt] + 64];
            acc[nt][2] = 0.f;
            acc[nt][3] = 0.f;
        }

        if (t > 0) MBAR_WAIT_CL(mbar, (t - 1) & 1);

        const uint32_t abase = hb32 + (uint32_t)(cur * 8 * HS1 * 2) + lmbase;
        #pragma unroll
        for (int kt = 0; kt < 8; ++kt) {
            uint32_t a0, a2;
            LDMATRIX_X2(a0, a2, abase + (uint32_t)(kt * 32));
            uint32_t afr[4] = {a0, 0u, a2, 0u};
            #pragma unroll
            for (int nt = 0; nt < 2; ++nt)
                mma_fp16(acc[nt], afr, bfr[nt][kt]);
        }

        float* yb = ybuf + (t & 1) * 8 * 68;
        #pragma unroll
        for (int nt = 0; nt < 2; ++nt) {
            float v0 = isState ? fmaxf(acc[nt][0], 0.f) : sigf(acc[nt][0]);
            float v1 = sigf(acc[nt][1]);
            float s0 = __shfl_xor_sync(0xffffffffu, v0, 1);
            float s1 = __shfl_xor_sync(0xffffffffu, v1, 1);
            if (isState) {
                float c0 = s1 * cst[nt] + s0 * v0;
                cst[nt] = c0;
                float h0 = v1 * fmaxf(c0, 0.f);
                __half h0h = __float2half(h0);
                int o0 = nxt * 8 * HS1 + r * HS1 + hj[nt];
                hbufh[o0] = h0h;
                peer_h[o0] = h0h;
                yb[r * 68 + al[nt]] = h0;
            }
        }

        if (t + 2 < 512) { CP_WAIT(1); }
        else             { CP_WAIT(0); }
    }

    // keep CTA alive until peer's final-step DSMEM writes complete
    __syncthreads();
    CLUSTER_ARRIVE();
    store_Y(511);
    CLUSTER_WAIT();
}

// ------ LSTM layer 2 (H=64) — R15 + ldmatrix.x2, single CTA -----------------
#define XS2 260
#define HS2 72
__global__ void __launch_bounds__(512, 1)
lstm2_mma_kernel(const float* __restrict__ xg2f, const float* __restrict__ xg2b,
                 const float* __restrict__ r2f,  const float* __restrict__ r2b,
                 float* __restrict__ hout)
{
    extern __shared__ char smraw[];
    float*  sxg   = (float*)smraw;                     // 3*8*XS2 f32
    __half* hbufh = (__half*)(smraw + 3*8*XS2*4);      // 2*8*HS2 f16

    const int dir = blockIdx.y;
    const int b0  = blockIdx.x * 8;
    const int tid = threadIdx.x;
    const int lane = tid & 31, w = tid >> 5;           // 0..15
    const int q = lane & 3;
    const float* xg = dir ? xg2b : xg2f;
    const float* Wr = dir ? r2b : r2f;

    uint32_t bfr[2][4][2];
    #pragma unroll
    for (int nt = 0; nt < 2; ++nt) {
        int n_local = w * 16 + nt * 8 + (lane >> 2);
        int G = (n_local & 3) * 64 + (n_local >> 2);
        #pragma unroll
        for (int kt = 0; kt < 4; ++kt)
            #pragma unroll
            for (int p = 0; p < 2; ++p) {
                int k = kt * 16 + q * 2 + p * 8;
                bfr[nt][kt][p] = pack_h2(__float2half(Wr[k * 256 + G]),
                                         __float2half(Wr[(k + 1) * 256 + G]));
            }
    }

    for (int i = tid; i < 2 * 8 * HS2; i += 512) hbufh[i] = __float2half(0.f);

    const uint32_t hb32 = smem_u32(hbufh);
    const uint32_t xbase = smem_u32(sxg);
    const uint32_t lmbase = (uint32_t)(((lane & 7) * HS2 + (((lane >> 3) & 1) << 3)) * 2);
    const bool isState = (lane & 1);
    const int g0 = (q & 1) * 2;
    int colA[2], hj[2];
    #pragma unroll
    for (int nt = 0; nt < 2; ++nt) {
        int a_local = w * 4 + nt * 2 + (q >> 1);
        colA[nt] = g0 * 64 + a_local;
        hj[nt]   = a_local;
    }
    const int r = lane >> 2;

    float cst[2] = {0.f, 0.f};

    auto issue_xg = [&](int tt, int stage) {
        const uint32_t dst0 = xbase + (uint32_t)(stage * 8 * XS2 * 4);
        int row = tid >> 6, c4 = tid & 63;
        CP_ASYNC16(dst0 + (uint32_t)((row * XS2 + c4 * 4) * 4),
                   xg + ((size_t)(b0 + row) * 512 + tt) * 256 + c4 * 4);
        CP_COMMIT();
    };

    __syncthreads();
    issue_xg(dir ? 511 : 0, 0);
    issue_xg(dir ? 510 : 1, 1);
    CP_WAIT(1);

    for (int t = 0; t < 512; ++t) {
        const int tt  = dir ? (511 - t) : t;
        const int cur = t & 1, nxt = cur ^ 1;

        __syncthreads();   // single barrier per step

        if (t + 2 < 512) issue_xg(dir ? (509 - t) : (t + 2), (t + 2) % 3);

        const float* xs = sxg + (t % 3) * 8 * XS2;
        float acc[2][4];
        #pragma unroll
        for (int nt = 0; nt < 2; ++nt) {
            acc[nt][0] = xs[r * XS2 + colA[nt]];
            acc[nt][1] = xs[r * XS2 + colA[nt] + 64];
            acc[nt][2] = 0.f;
            acc[nt][3] = 0.f;
        }

        const uint32_t abase = hb32 + (uint32_t)(cur * 8 * HS2 * 2) + lmbase;
        #pragma unroll
        for (int kt = 0; kt < 4; ++kt) {
            uint32_t a0, a2;
            LDMATRIX_X2(a0, a2, abase + (uint32_t)(kt * 32));
            uint32_t afr[4] = {a0, 0u, a2, 0u};
            #pragma unroll
            for (int nt = 0; nt < 2; ++nt)
                mma_fp16(acc[nt], afr, bfr[nt][kt]);
        }

        #pragma unroll
        for (int nt = 0; nt < 2; ++nt) {
            float v0 = isState ? fmaxf(acc[nt][0], 0.f) : sigf(acc[nt][0]);
            float v1 = sigf(acc[nt][1]);
            float s0 = __shfl_xor_sync(0xffffffffu, v0, 1);
            float s1 = __shfl_xor_sync(0xffffffffu, v1, 1);
            if (isState) {
                float c0 = s1 * cst[nt] + s0 * v0;
                cst[nt] = c0;
                float h0 = v1 * fmaxf(c0, 0.f);
                hbufh[nxt * 8 * HS2 + r * HS2 + hj[nt]] = __float2half(h0);
                if (t == 511)
                    hout[(size_t)(b0 + r) * 128 + dir * 64 + hj[nt]] = h0;
            }
        }

        if (t + 2 < 512) { CP_WAIT(1); }
        else             { CP_WAIT(0); }
    }
}

// ------------------------------ heads ---------------------------------------
__global__ void __launch_bounds__(256)
head_kernel(const float* __restrict__ x64, const float* __restrict__ h2,
            const float* __restrict__ wz1, const float* __restrict__ bz1,
            const float* __restrict__ wz2, const float* __restrict__ bz2,
            const float* __restrict__ wt1, const float* __restrict__ bt1,
            const float* __restrict__ wt2, const float* __restrict__ bt2,
            float* __restrict__ out)
{
    const int b = threadIdx.x;
    float comb[192];
    #pragma unroll 4
    for (int k = 0; k < 64; ++k)  comb[k]      = x64[b*64 + k];
    #pragma unroll 4
    for (int k = 0; k < 128; ++k) comb[64 + k] = h2[b*128 + k];

    float z0 = bz1[0], z1 = bz1[1], t0 = bt1[0], t1 = bt1[1];
    #pragma unroll 4
    for (int k = 0; k < 192; ++k) {
        float v = comb[k];
        z0 += v * wz1[k*2 + 0]; z1 += v * wz1[k*2 + 1];
        t0 += v * wt1[k*2 + 0]; t1 += v * wt1[k*2 + 1];
    }
    out[b]       = fmaxf(z0,0.f)*wz2[0] + fmaxf(z1,0.f)*wz2[1] + bz2[0];
    out[256 + b] = fmaxf(t0,0.f)*wt2[0] + fmaxf(t1,0.f)*wt2[1] + bt2[0];
}

// ------------------------------ launcher ------------------------------------
extern "C" void kernel_launch(void* const* d_in, const int* in_sizes, int n_in,
                              void* d_out, int out_size)
{
    const int*   inputA = (const int*)  d_in[0];
    const float* inputB = (const float*)d_in[1];
    const float* emb = (const float*)d_in[2];
    const float *w1=(const float*)d_in[3],  *b1=(const float*)d_in[4];
    const float *w2=(const float*)d_in[5],  *b2=(const float*)d_in[6];
    const float *w3=(const float*)d_in[7],  *b3=(const float*)d_in[8];
    const float *k1f=(const float*)d_in[9],  *r1f=(const float*)d_in[10], *bb1f=(const float*)d_in[11];
    const float *k1b=(const float*)d_in[12], *r1b=(const float*)d_in[13], *bb1b=(const float*)d_in[14];
    const float *k2f=(const float*)d_in[15], *r2f=(const float*)d_in[16], *bb2f=(const float*)d_in[17];
    const float *k2b=(const float*)d_in[18], *r2b=(const float*)d_in[19], *bb2b=(const float*)d_in[20];
    const float *wz1=(const float*)d_in[21], *bz1=(const float*)d_in[22];
    const float *wz2=(const float*)d_in[23], *bz2=(const float*)d_in[24];
    const float *wt1=(const float*)d_in[25], *bt1=(const float*)d_in[26];
    const float *wt2=(const float*)d_in[27], *bt2=(const float*)d_in[28];
    float* out = (float*)d_out;

    float *xg1f, *xg1b, *xg2f, *xg2b, *x64, *h2;
    __half *xBhi, *xBlo, *Yhi, *Ylo, *wTh;
    cudaGetSymbolAddress((void**)&xg1f, g_xg1f);
    cudaGetSymbolAddress((void**)&xg1b, g_xg1b);
    cudaGetSymbolAddress((void**)&xg2f, g_xg2f);
    cudaGetSymbolAddress((void**)&xg2b, g_xg2b);
    cudaGetSymbolAddress((void**)&x64,  g_x64);
    cudaGetSymbolAddress((void**)&h2,   g_h2);
    cudaGetSymbolAddress((void**)&xBhi, g_xBhi);
    cudaGetSymbolAddress((void**)&xBlo, g_xBlo);
    cudaGetSymbolAddress((void**)&Yhi,  g_Yhi);
    cudaGetSymbolAddress((void**)&Ylo,  g_Ylo);
    cudaGetSymbolAddress((void**)&wTh,  g_wTh);

    __half *w1fh = wTh,            *w1bh = wTh + 65536;
    __half *w2fh = wTh + 2*65536,  *w2bh = wTh + 3*65536;

    const size_t sm1 = (size_t)(3*8*XS1P*4 + 2*8*HS1*2 + 2*8*68*4 + 16);
    const size_t sm2 = (size_t)(3*8*XS2*4 + 2*8*HS2*2);

    static bool attr_done = false;
    if (!attr_done) {
        cudaFuncSetAttribute(gemm_fp16_kernel, cudaFuncAttributeMaxDynamicSharedMemorySize, 2*GSTAGE);
        cudaFuncSetAttribute(lstm1_mma_kernel, cudaFuncAttributeMaxDynamicSharedMemorySize, (int)sm1);
        cudaFuncSetAttribute(lstm2_mma_kernel, cudaFuncAttributeMaxDynamicSharedMemorySize, (int)sm2);
        attr_done = true;
    }

    prep_kernel<<<(SPLIT_N4 + 4*65536 + 255)/256, 256>>>(inputB, xBhi, xBlo,
                                                         k1f, k1b, k2f, k2b, wTh);  // 0
    const size_t gsm = 2*GSTAGE;
    gemm_fp16_kernel<<<dim3(1024,4), 256, gsm>>>(xBhi, xBlo, w1fh, bb1f, xg1f, BT, 512, 128); // 1
    gemm_fp16_kernel<<<dim3(1024,4), 256, gsm>>>(xBhi, xBlo, w1bh, bb1b, xg1b, BT, 512, 128); // 2

    lstm1_mma_kernel<<<dim3(64,2), 512, sm1>>>(xg1f, xg1b, r1f, r1b, Yhi, Ylo);     // 3

    gemm_fp16_kernel<<<dim3(1024,2), 256, gsm>>>(Yhi, Ylo, w2fh, bb2f, xg2f, BT, 256, 256);   // 4
    gemm_fp16_kernel<<<dim3(1024,2), 256, gsm>>>(Yhi, Ylo, w2bh, bb2b, xg2b, BT, 256, 256);   // 5

    lstm2_mma_kernel<<<dim3(32,2), 512, sm2>>>(xg2f, xg2b, r2f, r2b, h2);           // 6

    emb_mlp_kernel<<<256, 256>>>(inputA, emb, w1,b1, w2,b2, w3,b3, x64);            // 7
    head_kernel<<<1, 256>>>(x64, h2, wz1,bz1, wz2,bz2, wt1,bt1, wt2,bt2, out);      // 8
}